// round 5
// baseline (speedup 1.0000x reference)
#include <cuda_runtime.h>
#include <math.h>

#define NG    4096
#define IW    96
#define IH    96
#define NPIX  (IW*IH)
#define NTILE 36            // 6x6 tiles of 16x16
#define RCH   16            // depth chunks for render parallelism
#define RCHSZ (NG/RCH)      // 256
#define GRID  (NTILE*RCH)   // 576 blocks, all resident (4/SM x 148 = 592)
#define TANFOV 0.36502849177392513f
#define LIMV   (1.3f*TANFOV)
#define FXY    (96.0f/(2.0f*TANFOV))
#define INV255 0.0039215686274509803f

typedef unsigned long long u64;

// ---------------- scratch (no allocations allowed) ----------------
__device__ float4 g_p0[NG], g_p1[NG], g_p3[NG];   // unsorted packed params (+bbox)
__device__ float2 g_p2[NG];
__device__ u64    g_key[NG];
__device__ int    g_tilecnt[NTILE];
__device__ float4 g_s0[NG], g_s1[NG], g_s3[NG];   // sorted
__device__ float2 g_s2[NG];
__device__ float  g_partial[RCH * 4 * NTILE * 256];
__device__ int          g_bar_cnt[2];
__device__ volatile int g_bar_gen[2];

// replay-safe grid barrier: 1 atomic arrival per block, VOLATILE-LOAD polling
// (no atomic-ALU spin storm), nanosleep backoff. gen is monotone across replays;
// cnt self-resets to 0 each pass.
__device__ __forceinline__ void grid_bar(int slot) {
    __syncthreads();
    if (threadIdx.x == 0) {
        int gen = g_bar_gen[slot];
        __threadfence();
        if (atomicAdd(&g_bar_cnt[slot], 1) == GRID - 1) {
            g_bar_cnt[slot] = 0;
            __threadfence();
            g_bar_gen[slot] = gen + 1;
        } else {
            while (g_bar_gen[slot] == gen) __nanosleep(128);
            __threadfence();
        }
    }
    __syncthreads();
}

__global__ __launch_bounds__(256, 4)
void fused_kernel(const float* __restrict__ means,
                  const float* __restrict__ scales_raw,
                  const float* __restrict__ rots,
                  const float* __restrict__ op_raw,
                  const float* __restrict__ shs,
                  const float* __restrict__ view,
                  const float* __restrict__ proj,
                  const float* __restrict__ campos,
                  const float* __restrict__ bg,
                  float* __restrict__ out)
{
    __shared__ union {
        float  mats[2048];                    // phase A: view/proj staging
        u64    keys[2048];                    // phase B: key staging (16 KB)
        struct {
            float4 c0[256];
            float4 c1[256];
            float2 c2[256];
            int wcnt[8];
            int sdone;
        } r;                                  // phase C
    } su;

    int blk = blockIdx.x;
    int t   = threadIdx.x;

    // ================= Phase A: preprocess (+ per-replay resets) =================
    {
        // stage matrices in smem to relieve register pressure under the 64-reg cap
        if (t < 16)              su.mats[t]      = view[t];
        else if (t < 32)         su.mats[t]      = proj[t - 16];
        __syncthreads();
        const float* v = su.mats;
        const float* p = su.mats + 16;

        int n = blk * 256 + t;
        if (n < NG) {
            if (n < NTILE) g_tilecnt[n] = 0;

            float mx = means[3*n+0], my = means[3*n+1], mz = means[3*n+2];
            float sx = __expf(scales_raw[3*n+0]);
            float sy = __expf(scales_raw[3*n+1]);
            float sz = __expf(scales_raw[3*n+2]);

            float qr = rots[4*n+0], qx = rots[4*n+1], qy = rots[4*n+2], qz = rots[4*n+3];
            float qn = rsqrtf(qr*qr + qx*qx + qy*qy + qz*qz);
            qr *= qn; qx *= qn; qy *= qn; qz *= qn;

            float R00 = 1.f - 2.f*(qy*qy + qz*qz);
            float R01 = 2.f*(qx*qy - qr*qz);
            float R02 = 2.f*(qx*qz + qr*qy);
            float R10 = 2.f*(qx*qy + qr*qz);
            float R11 = 1.f - 2.f*(qx*qx + qz*qz);
            float R12 = 2.f*(qy*qz - qr*qx);
            float R20 = 2.f*(qx*qz - qr*qy);
            float R21 = 2.f*(qy*qz + qr*qx);
            float R22 = 1.f - 2.f*(qx*qx + qy*qy);

            float L00 = R00*sx, L01 = R01*sy, L02 = R02*sz;
            float L10 = R10*sx, L11 = R11*sy, L12 = R12*sz;
            float L20 = R20*sx, L21 = R21*sy, L22 = R22*sz;
            float S00 = L00*L00 + L01*L01 + L02*L02;
            float S01 = L00*L10 + L01*L11 + L02*L12;
            float S02 = L00*L20 + L01*L21 + L02*L22;
            float S11 = L10*L10 + L11*L11 + L12*L12;
            float S12 = L10*L20 + L11*L21 + L12*L22;
            float S22 = L20*L20 + L21*L21 + L22*L22;

            float pv0 = v[0]*mx + v[1]*my + v[2]*mz + v[3];
            float pv1 = v[4]*mx + v[5]*my + v[6]*mz + v[7];
            float pv2 = v[8]*mx + v[9]*my + v[10]*mz + v[11];
            float depth = pv2;

            float ph0 = p[0]*mx + p[1]*my + p[2]*mz + p[3];
            float ph1 = p[4]*mx + p[5]*my + p[6]*mz + p[7];
            float ph3 = p[12]*mx + p[13]*my + p[14]*mz + p[15];
            float pw  = 1.f / (ph3 + 1e-7f);
            float mxs = ((ph0*pw + 1.f) * (float)IW - 1.f) * 0.5f;
            float mys = ((ph1*pw + 1.f) * (float)IH - 1.f) * 0.5f;

            float tz = depth;
            float invtz = 1.f / tz;
            float txc = fminf(fmaxf(pv0*invtz, -LIMV), LIMV) * tz;
            float tyc = fminf(fmaxf(pv1*invtz, -LIMV), LIMV) * tz;
            float J00 = FXY * invtz;
            float J02 = -FXY * txc * invtz * invtz;
            float J11 = FXY * invtz;
            float J12 = -FXY * tyc * invtz * invtz;

            float M00 = J00*v[0] + J02*v[8];
            float M01 = J00*v[1] + J02*v[9];
            float M02 = J00*v[2] + J02*v[10];
            float M10 = J11*v[4] + J12*v[8];
            float M11 = J11*v[5] + J12*v[9];
            float M12 = J11*v[6] + J12*v[10];

            float t00 = M00*S00 + M01*S01 + M02*S02;
            float t01 = M00*S01 + M01*S11 + M02*S12;
            float t02 = M00*S02 + M01*S12 + M02*S22;
            float t10 = M10*S00 + M11*S01 + M12*S02;
            float t11 = M10*S01 + M11*S11 + M12*S12;
            float t12 = M10*S02 + M11*S12 + M12*S22;
            float cov00 = t00*M00 + t01*M01 + t02*M02;
            float cov01 = t00*M10 + t01*M11 + t02*M12;
            float cov11 = t10*M10 + t11*M11 + t12*M12;

            float a  = cov00 + 0.3f;
            float bb = cov01;
            float c  = cov11 + 0.3f;
            float det = a*c - bb*bb;

            float op = 1.f / (1.f + __expf(-op_raw[n]));

            float dx0 = mx - campos[0], dy0 = my - campos[1], dz0 = mz - campos[2];
            float rn = rsqrtf(dx0*dx0 + dy0*dy0 + dz0*dz0);
            float x = dx0*rn, y = dy0*rn, z = dz0*rn;
            float xx = x*x, yy = y*y, zz = z*z;
            float xy = x*y, yz = y*z, xz = x*z;

            const float C0f = 0.28209479177387814f;
            const float C1f = 0.4886025119029199f;
            const float C2f0 = 1.0925484305920792f, C2f1 = -1.0925484305920792f;
            const float C2f2 = 0.31539156525252005f, C2f3 = -1.0925484305920792f;
            const float C2f4 = 0.5462742152960396f;
            const float C3f0 = -0.5900435899266435f, C3f1 = 2.890611442640554f;
            const float C3f2 = -0.4570457994644658f, C3f3 = 0.3731763325901154f;
            const float C3f4 = -0.4570457994644658f, C3f5 = 1.445305721320277f;
            const float C3f6 = -0.5900435899266435f;

            float col[3];
            const float* shb = shs + n*48;
            #pragma unroll
            for (int ch = 0; ch < 3; ch++) {
                float s0  = shb[0*3+ch],  s1  = shb[1*3+ch],  s2  = shb[2*3+ch],  s3  = shb[3*3+ch];
                float s4  = shb[4*3+ch],  s5  = shb[5*3+ch],  s6  = shb[6*3+ch],  s7  = shb[7*3+ch];
                float s8  = shb[8*3+ch],  s9  = shb[9*3+ch],  s10 = shb[10*3+ch], s11 = shb[11*3+ch];
                float s12 = shb[12*3+ch], s13 = shb[13*3+ch], s14 = shb[14*3+ch], s15 = shb[15*3+ch];
                float res = C0f*s0
                          - C1f*y*s1 + C1f*z*s2 - C1f*x*s3
                          + C2f0*xy*s4 + C2f1*yz*s5 + C2f2*(2.f*zz - xx - yy)*s6
                          + C2f3*xz*s7 + C2f4*(xx - yy)*s8
                          + C3f0*y*(3.f*xx - yy)*s9 + C3f1*xy*z*s10
                          + C3f2*y*(4.f*zz - xx - yy)*s11
                          + C3f3*z*(2.f*zz - 3.f*xx - 3.f*yy)*s12
                          + C3f4*x*(4.f*zz - xx - yy)*s13
                          + C3f5*z*(xx - yy)*s14 + C3f6*x*(xx - 3.f*yy)*s15;
                col[ch] = fmaxf(res + 0.5f, 0.f);
            }

            bool valid = (depth > 0.2f) && (det > 0.f);
            float A, B, C, pth;
            float bxmin = 1e9f, bxmax = -1e9f, bymin = 1e9f, bymax = -1e9f;
            float q2 = __logf(255.f * op) + 0.02f;
            if (valid && q2 > 0.f) {
                float invdet = 1.f / det;
                A = c * invdet;
                B = -bb * invdet;
                C = a * invdet;
                pth = -q2;
                float dxm = sqrtf(2.f * q2 * a) + 1e-3f;
                float dym = sqrtf(2.f * q2 * c) + 1e-3f;
                bxmin = mxs - dxm; bxmax = mxs + dxm;
                bymin = mys - dym; bymax = mys + dym;
            } else {
                mxs = 0.f; mys = 0.f;
                A = 0.f; B = 0.f; C = 0.f;
                op = 0.f;
                pth = 1.0f;
            }

            g_p0[n] = make_float4(mxs, mys, A, B);
            g_p1[n] = make_float4(C, op, col[0], col[1]);
            g_p2[n] = make_float2(col[2], pth);
            g_p3[n] = make_float4(bxmin, bxmax, bymin, bymax);

            unsigned int b32 = __float_as_uint(depth);
            b32 ^= (b32 >> 31) ? 0xFFFFFFFFu : 0x80000000u;
            g_key[n] = ((u64)b32 << 32) | (unsigned int)n;
        }
    }

    grid_bar(0);

    // ================= Phase B: rank sort + scatter (blocks 0..127) =================
    if (blk < 128) {
        int elem  = blk * 32 + (t >> 3);
        int slice = t & 7;
        u64 myk = g_key[elem];
        int cnt = 0;
        #pragma unroll
        for (int st = 0; st < 2; st++) {
            #pragma unroll
            for (int u = 0; u < 8; u++)
                su.keys[u*256 + t] = g_key[st*2048 + u*256 + t];
            __syncthreads();
            int kb = slice * 256;
            #pragma unroll 8
            for (int j = 0; j < 256; j++)
                cnt += (su.keys[kb + j] < myk) ? 1 : 0;
            __syncthreads();
        }
        cnt += __shfl_xor_sync(0xffffffffu, cnt, 1);
        cnt += __shfl_xor_sync(0xffffffffu, cnt, 2);
        cnt += __shfl_xor_sync(0xffffffffu, cnt, 4);
        if (slice == 0) {
            g_s0[cnt] = g_p0[elem];
            g_s1[cnt] = g_p1[elem];
            g_s2[cnt] = g_p2[elem];
            g_s3[cnt] = g_p3[elem];
        }
    }

    grid_bar(1);

    // ================= Phase C: tiled render + fused combine =================
    int tile  = blk >> 4;          // 0..35
    int chunk = blk & 15;          // 0..15
    int w = t >> 5, lane = t & 31;

    float tx0 = (float)((tile % 6) * 16);
    float ty0 = (float)((tile / 6) * 16);
    float tx1 = tx0 + 15.f;
    float ty1 = ty0 + 15.f;
    float px = tx0 + (float)(t & 15);
    float py = ty0 + (float)(t >> 4);

    float T = 1.f, cr = 0.f, cg = 0.f, cb = 0.f;

    int gi = chunk * RCHSZ + t;
    float4 bbx = g_s3[gi];
    bool hit = (bbx.x <= tx1) && (bbx.y >= tx0) && (bbx.z <= ty1) && (bbx.w >= ty0);
    unsigned int bal = __ballot_sync(0xffffffffu, hit);
    if (lane == 0) su.r.wcnt[w] = __popc(bal);
    __syncthreads();

    int off = 0, m = 0;
    #pragma unroll
    for (int i = 0; i < 8; i++) {
        int cnt = su.r.wcnt[i];
        if (i < w) off += cnt;
        m += cnt;
    }
    if (hit) {
        int pos = off + __popc(bal & ((1u << lane) - 1u));
        su.r.c0[pos] = g_s0[gi];
        su.r.c1[pos] = g_s1[gi];
        su.r.c2[pos] = g_s2[gi];
    }
    __syncthreads();

    for (int i = 0; i < m; i++) {
        float4 a0 = su.r.c0[i];
        float2 a2 = su.r.c2[i];
        float dx = px - a0.x;
        float dy = py - a0.y;
        float4 a1 = su.r.c1[i];
        float power = -0.5f * (a0.z*dx*dx + a1.x*dy*dy) - a0.w*dx*dy;
        if (power < a2.y) continue;
        float alpha = fminf(0.99f, a1.y * __expf(power));
        if (alpha < INV255) continue;
        float wgt = alpha * T;
        cr = fmaf(wgt, a1.z, cr);
        cg = fmaf(wgt, a1.w, cg);
        cb = fmaf(wgt, a2.x, cb);
        T *= (1.f - alpha);
    }

    int pbase = (chunk * 4) * (NTILE * 256) + tile * 256 + t;
    g_partial[pbase]                 = cr;
    g_partial[pbase + NTILE*256]     = cg;
    g_partial[pbase + 2*NTILE*256]   = cb;
    g_partial[pbase + 3*NTILE*256]   = T;

    __threadfence();
    if (t == 0) su.r.sdone = atomicAdd(&g_tilecnt[tile], 1);
    __syncthreads();
    if (su.r.sdone == RCH - 1) {
        __threadfence();
        float Tt = 1.f, r = 0.f, g = 0.f, b = 0.f;
        #pragma unroll
        for (int k = 0; k < RCH; k++) {
            int pb = (k * 4) * (NTILE * 256) + tile * 256 + t;
            r += Tt * g_partial[pb];
            g += Tt * g_partial[pb + NTILE*256];
            b += Tt * g_partial[pb + 2*NTILE*256];
            Tt *= g_partial[pb + 3*NTILE*256];
        }
        int pix = ((tile / 6) * 16 + (t >> 4)) * IW + (tile % 6) * 16 + (t & 15);
        out[pix]          = r + Tt * bg[0];
        out[NPIX + pix]   = g + Tt * bg[1];
        out[2*NPIX + pix] = b + Tt * bg[2];
    }
}

extern "C" void kernel_launch(void* const* d_in, const int* in_sizes, int n_in,
                              void* d_out, int out_size)
{
    const float* means      = (const float*)d_in[0];
    const float* scales_raw = (const float*)d_in[1];
    const float* rots       = (const float*)d_in[2];
    const float* op_raw     = (const float*)d_in[3];
    const float* shs        = (const float*)d_in[4];
    const float* view       = (const float*)d_in[5];
    const float* proj       = (const float*)d_in[6];
    const float* campos     = (const float*)d_in[7];
    const float* bg         = (const float*)d_in[8];
    float* out = (float*)d_out;

    fused_kernel<<<GRID, 256>>>(means, scales_raw, rots, op_raw, shs,
                                view, proj, campos, bg, out);
}

// round 6
// speedup vs baseline: 1.5713x; 1.5713x over previous
#include <cuda_runtime.h>
#include <math.h>

#define NG    4096
#define IW    96
#define IH    96
#define NPIX  (IW*IH)
#define NTILE 36            // 6x6 tiles of 16x16
#define RCH   16            // depth chunks for render parallelism
#define RCHSZ (NG/RCH)      // 256
#define TANFOV 0.36502849177392513f
#define LIMV   (1.3f*TANFOV)
#define FXY    (96.0f/(2.0f*TANFOV))
#define INV255 0.0039215686274509803f

typedef unsigned long long u64;

// ---------------- scratch (no allocations allowed) ----------------
__device__ float4 g_p0[NG], g_p1[NG], g_p3[NG];   // unsorted packed params (+bbox)
__device__ float2 g_p2[NG];
__device__ u64    g_key[NG];
__device__ int    g_tilecnt[NTILE];
__device__ float4 g_s0[NG], g_s1[NG], g_s3[NG];   // sorted
__device__ float2 g_s2[NG];
__device__ float  g_partial[RCH * 4 * NTILE * 256];

// ---------------- 1) per-gaussian preprocess ----------------
__global__ __launch_bounds__(256)
void preprocess_kernel(const float* __restrict__ means,
                       const float* __restrict__ scales_raw,
                       const float* __restrict__ rots,
                       const float* __restrict__ op_raw,
                       const float* __restrict__ shs,
                       const float* __restrict__ view,
                       const float* __restrict__ proj,
                       const float* __restrict__ campos)
{
    int n = blockIdx.x * blockDim.x + threadIdx.x;
    if (n >= NG) return;
    if (n < NTILE) g_tilecnt[n] = 0;   // per-replay reset for tail combine

    float mx = means[3*n+0], my = means[3*n+1], mz = means[3*n+2];
    float sx = __expf(scales_raw[3*n+0]);
    float sy = __expf(scales_raw[3*n+1]);
    float sz = __expf(scales_raw[3*n+2]);

    float qr = rots[4*n+0], qx = rots[4*n+1], qy = rots[4*n+2], qz = rots[4*n+3];
    float qn = rsqrtf(qr*qr + qx*qx + qy*qy + qz*qz);
    qr *= qn; qx *= qn; qy *= qn; qz *= qn;

    float R00 = 1.f - 2.f*(qy*qy + qz*qz);
    float R01 = 2.f*(qx*qy - qr*qz);
    float R02 = 2.f*(qx*qz + qr*qy);
    float R10 = 2.f*(qx*qy + qr*qz);
    float R11 = 1.f - 2.f*(qx*qx + qz*qz);
    float R12 = 2.f*(qy*qz - qr*qx);
    float R20 = 2.f*(qx*qz - qr*qy);
    float R21 = 2.f*(qy*qz + qr*qx);
    float R22 = 1.f - 2.f*(qx*qx + qy*qy);

    float L00 = R00*sx, L01 = R01*sy, L02 = R02*sz;
    float L10 = R10*sx, L11 = R11*sy, L12 = R12*sz;
    float L20 = R20*sx, L21 = R21*sy, L22 = R22*sz;
    float S00 = L00*L00 + L01*L01 + L02*L02;
    float S01 = L00*L10 + L01*L11 + L02*L12;
    float S02 = L00*L20 + L01*L21 + L02*L22;
    float S11 = L10*L10 + L11*L11 + L12*L12;
    float S12 = L10*L20 + L11*L21 + L12*L22;
    float S22 = L20*L20 + L21*L21 + L22*L22;

    float v[16], p[16];
    #pragma unroll
    for (int i = 0; i < 16; i++) { v[i] = view[i]; p[i] = proj[i]; }

    float pv0 = v[0]*mx + v[1]*my + v[2]*mz + v[3];
    float pv1 = v[4]*mx + v[5]*my + v[6]*mz + v[7];
    float pv2 = v[8]*mx + v[9]*my + v[10]*mz + v[11];
    float depth = pv2;

    float ph0 = p[0]*mx + p[1]*my + p[2]*mz + p[3];
    float ph1 = p[4]*mx + p[5]*my + p[6]*mz + p[7];
    float ph3 = p[12]*mx + p[13]*my + p[14]*mz + p[15];
    float pw  = 1.f / (ph3 + 1e-7f);
    float mxs = ((ph0*pw + 1.f) * (float)IW - 1.f) * 0.5f;
    float mys = ((ph1*pw + 1.f) * (float)IH - 1.f) * 0.5f;

    float tz = depth;
    float invtz = 1.f / tz;
    float txc = fminf(fmaxf(pv0*invtz, -LIMV), LIMV) * tz;
    float tyc = fminf(fmaxf(pv1*invtz, -LIMV), LIMV) * tz;
    float J00 = FXY * invtz;
    float J02 = -FXY * txc * invtz * invtz;
    float J11 = FXY * invtz;
    float J12 = -FXY * tyc * invtz * invtz;

    float M00 = J00*v[0] + J02*v[8];
    float M01 = J00*v[1] + J02*v[9];
    float M02 = J00*v[2] + J02*v[10];
    float M10 = J11*v[4] + J12*v[8];
    float M11 = J11*v[5] + J12*v[9];
    float M12 = J11*v[6] + J12*v[10];

    float t00 = M00*S00 + M01*S01 + M02*S02;
    float t01 = M00*S01 + M01*S11 + M02*S12;
    float t02 = M00*S02 + M01*S12 + M02*S22;
    float t10 = M10*S00 + M11*S01 + M12*S02;
    float t11 = M10*S01 + M11*S11 + M12*S12;
    float t12 = M10*S02 + M11*S12 + M12*S22;
    float cov00 = t00*M00 + t01*M01 + t02*M02;
    float cov01 = t00*M10 + t01*M11 + t02*M12;
    float cov11 = t10*M10 + t11*M11 + t12*M12;

    float a  = cov00 + 0.3f;
    float bb = cov01;
    float c  = cov11 + 0.3f;
    float det = a*c - bb*bb;

    float op = 1.f / (1.f + __expf(-op_raw[n]));

    float dx0 = mx - campos[0], dy0 = my - campos[1], dz0 = mz - campos[2];
    float rn = rsqrtf(dx0*dx0 + dy0*dy0 + dz0*dz0);
    float x = dx0*rn, y = dy0*rn, z = dz0*rn;
    float xx = x*x, yy = y*y, zz = z*z;
    float xy = x*y, yz = y*z, xz = x*z;

    const float C0f = 0.28209479177387814f;
    const float C1f = 0.4886025119029199f;
    const float C2f0 = 1.0925484305920792f, C2f1 = -1.0925484305920792f;
    const float C2f2 = 0.31539156525252005f, C2f3 = -1.0925484305920792f;
    const float C2f4 = 0.5462742152960396f;
    const float C3f0 = -0.5900435899266435f, C3f1 = 2.890611442640554f;
    const float C3f2 = -0.4570457994644658f, C3f3 = 0.3731763325901154f;
    const float C3f4 = -0.4570457994644658f, C3f5 = 1.445305721320277f;
    const float C3f6 = -0.5900435899266435f;

    float col[3];
    const float* shb = shs + n*48;
    #pragma unroll
    for (int ch = 0; ch < 3; ch++) {
        float s0  = shb[0*3+ch],  s1  = shb[1*3+ch],  s2  = shb[2*3+ch],  s3  = shb[3*3+ch];
        float s4  = shb[4*3+ch],  s5  = shb[5*3+ch],  s6  = shb[6*3+ch],  s7  = shb[7*3+ch];
        float s8  = shb[8*3+ch],  s9  = shb[9*3+ch],  s10 = shb[10*3+ch], s11 = shb[11*3+ch];
        float s12 = shb[12*3+ch], s13 = shb[13*3+ch], s14 = shb[14*3+ch], s15 = shb[15*3+ch];
        float res = C0f*s0
                  - C1f*y*s1 + C1f*z*s2 - C1f*x*s3
                  + C2f0*xy*s4 + C2f1*yz*s5 + C2f2*(2.f*zz - xx - yy)*s6
                  + C2f3*xz*s7 + C2f4*(xx - yy)*s8
                  + C3f0*y*(3.f*xx - yy)*s9 + C3f1*xy*z*s10
                  + C3f2*y*(4.f*zz - xx - yy)*s11
                  + C3f3*z*(2.f*zz - 3.f*xx - 3.f*yy)*s12
                  + C3f4*x*(4.f*zz - xx - yy)*s13
                  + C3f5*z*(xx - yy)*s14 + C3f6*x*(xx - 3.f*yy)*s15;
        col[ch] = fmaxf(res + 0.5f, 0.f);
    }

    bool valid = (depth > 0.2f) && (det > 0.f);
    float A, B, C, pth;
    float bxmin = 1e9f, bxmax = -1e9f, bymin = 1e9f, bymax = -1e9f;
    float q2 = __logf(255.f * op) + 0.02f;
    if (valid && q2 > 0.f) {
        float invdet = 1.f / det;
        A = c * invdet;
        B = -bb * invdet;
        C = a * invdet;
        pth = -q2;
        float dxm = sqrtf(2.f * q2 * a) + 1e-3f;
        float dym = sqrtf(2.f * q2 * c) + 1e-3f;
        bxmin = mxs - dxm; bxmax = mxs + dxm;
        bymin = mys - dym; bymax = mys + dym;
    } else {
        mxs = 0.f; mys = 0.f;
        A = 0.f; B = 0.f; C = 0.f;
        op = 0.f;
        pth = 1.0f;
    }

    g_p0[n] = make_float4(mxs, mys, A, B);
    g_p1[n] = make_float4(C, op, col[0], col[1]);
    g_p2[n] = make_float2(col[2], pth);
    g_p3[n] = make_float4(bxmin, bxmax, bymin, bymax);

    unsigned int b32 = __float_as_uint(depth);
    b32 ^= (b32 >> 31) ? 0xFFFFFFFFu : 0x80000000u;
    g_key[n] = ((u64)b32 << 32) | (unsigned int)n;
}

// ---------------- 2) fused rank sort + scatter (atomic-free) ----------------
// 128 blocks x 256 threads; 8 threads per element, each scans 512 keys from smem.
__global__ __launch_bounds__(256)
void rank_scatter_kernel()
{
    __shared__ u64 keys[2048];   // 16 KB staging, two halves
    int t = threadIdx.x;
    int blk = blockIdx.x;
    int elem  = blk * 32 + (t >> 3);
    int slice = t & 7;
    u64 myk = g_key[elem];
    int cnt = 0;
    #pragma unroll
    for (int st = 0; st < 2; st++) {
        #pragma unroll
        for (int u = 0; u < 8; u++)
            keys[u*256 + t] = g_key[st*2048 + u*256 + t];
        __syncthreads();
        int kb = slice * 256;
        #pragma unroll 8
        for (int j = 0; j < 256; j++)
            cnt += (keys[kb + j] < myk) ? 1 : 0;
        __syncthreads();
    }
    cnt += __shfl_xor_sync(0xffffffffu, cnt, 1);
    cnt += __shfl_xor_sync(0xffffffffu, cnt, 2);
    cnt += __shfl_xor_sync(0xffffffffu, cnt, 4);
    if (slice == 0) {
        g_s0[cnt] = g_p0[elem];
        g_s1[cnt] = g_p1[elem];
        g_s2[cnt] = g_p2[elem];
        g_s3[cnt] = g_p3[elem];
    }
}

// ---------------- 3) tiled render + fused tail combine ----------------
__global__ __launch_bounds__(256)
void render_tile_kernel(const float* __restrict__ bg, float* __restrict__ out)
{
    __shared__ float4 c0[256];
    __shared__ float4 c1[256];
    __shared__ float2 c2[256];
    __shared__ int wcnt[8];
    __shared__ int sdone;

    int tile  = blockIdx.x;
    int chunk = blockIdx.y;
    int t = threadIdx.x;
    int w = t >> 5, lane = t & 31;

    float tx0 = (float)((tile % 6) * 16);
    float ty0 = (float)((tile / 6) * 16);
    float tx1 = tx0 + 15.f;
    float ty1 = ty0 + 15.f;
    float px = tx0 + (float)(t & 15);
    float py = ty0 + (float)(t >> 4);

    float T = 1.f, cr = 0.f, cg = 0.f, cb = 0.f;

    int gi = chunk * RCHSZ + t;
    float4 bbx = g_s3[gi];
    bool hit = (bbx.x <= tx1) && (bbx.y >= tx0) && (bbx.z <= ty1) && (bbx.w >= ty0);
    unsigned int bal = __ballot_sync(0xffffffffu, hit);
    if (lane == 0) wcnt[w] = __popc(bal);
    __syncthreads();

    int off = 0, m = 0;
    #pragma unroll
    for (int i = 0; i < 8; i++) {
        int cnt = wcnt[i];
        if (i < w) off += cnt;
        m += cnt;
    }
    if (hit) {
        int pos = off + __popc(bal & ((1u << lane) - 1u));
        c0[pos] = g_s0[gi];
        c1[pos] = g_s1[gi];
        c2[pos] = g_s2[gi];
    }
    __syncthreads();

    for (int i = 0; i < m; i++) {
        float4 a0 = c0[i];
        float2 a2 = c2[i];
        float dx = px - a0.x;
        float dy = py - a0.y;
        float4 a1 = c1[i];
        float power = -0.5f * (a0.z*dx*dx + a1.x*dy*dy) - a0.w*dx*dy;
        if (power < a2.y) continue;          // conic pos-def => power<=0 always
        float alpha = fminf(0.99f, a1.y * __expf(power));
        if (alpha < INV255) continue;
        float wgt = alpha * T;
        cr = fmaf(wgt, a1.z, cr);
        cg = fmaf(wgt, a1.w, cg);
        cb = fmaf(wgt, a2.x, cb);
        T *= (1.f - alpha);
    }

    int pbase = (chunk * 4) * (NTILE * 256) + tile * 256 + t;
    g_partial[pbase]                 = cr;
    g_partial[pbase + NTILE*256]     = cg;
    g_partial[pbase + 2*NTILE*256]   = cb;
    g_partial[pbase + 3*NTILE*256]   = T;

    // last block per tile folds the chunks
    __threadfence();
    if (t == 0) sdone = atomicAdd(&g_tilecnt[tile], 1);
    __syncthreads();
    if (sdone == RCH - 1) {
        __threadfence();
        float Tt = 1.f, r = 0.f, g = 0.f, b = 0.f;
        #pragma unroll
        for (int k = 0; k < RCH; k++) {
            int pb = (k * 4) * (NTILE * 256) + tile * 256 + t;
            r += Tt * g_partial[pb];
            g += Tt * g_partial[pb + NTILE*256];
            b += Tt * g_partial[pb + 2*NTILE*256];
            Tt *= g_partial[pb + 3*NTILE*256];
        }
        int pix = ((tile / 6) * 16 + (t >> 4)) * IW + (tile % 6) * 16 + (t & 15);
        out[pix]          = r + Tt * bg[0];
        out[NPIX + pix]   = g + Tt * bg[1];
        out[2*NPIX + pix] = b + Tt * bg[2];
    }
}

extern "C" void kernel_launch(void* const* d_in, const int* in_sizes, int n_in,
                              void* d_out, int out_size)
{
    const float* means      = (const float*)d_in[0];
    const float* scales_raw = (const float*)d_in[1];
    const float* rots       = (const float*)d_in[2];
    const float* op_raw     = (const float*)d_in[3];
    const float* shs        = (const float*)d_in[4];
    const float* view       = (const float*)d_in[5];
    const float* proj       = (const float*)d_in[6];
    const float* campos     = (const float*)d_in[7];
    const float* bg         = (const float*)d_in[8];
    float* out = (float*)d_out;

    preprocess_kernel<<<NG/256, 256>>>(means, scales_raw, rots, op_raw, shs,
                                       view, proj, campos);
    rank_scatter_kernel<<<128, 256>>>();
    render_tile_kernel<<<dim3(NTILE, RCH), 256>>>(bg, out);
}

// round 8
// speedup vs baseline: 1.6790x; 1.0685x over previous
#include <cuda_runtime.h>
#include <math.h>

#define NG    4096
#define IW    96
#define IH    96
#define NPIX  (IW*IH)
#define NTILE 36            // 6x6 tiles of 16x16
#define RCH   16            // depth chunks for render parallelism
#define RCHSZ (NG/RCH)      // 256
#define TANFOV 0.36502849177392513f
#define LIMV   (1.3f*TANFOV)
#define FXY    (96.0f/(2.0f*TANFOV))
#define INV255 0.0039215686274509803f

typedef unsigned long long u64;

// ---------------- scratch (no allocations allowed) ----------------
__device__ float4 g_p0[NG], g_p1[NG], g_p3[NG];   // unsorted packed params (+bbox)
__device__ float2 g_p2[NG];
__device__ u64    g_key[NG];
__device__ float4 g_s0[NG], g_s1[NG], g_s3[NG];   // sorted
__device__ float2 g_s2[NG];
__device__ float  g_partial[RCH * 4 * NTILE * 256];

// ---------------- 1) per-gaussian preprocess (vectorized loads) ----------------
__global__ __launch_bounds__(128)
void preprocess_kernel(const float* __restrict__ means,
                       const float* __restrict__ scales_raw,
                       const float4* __restrict__ rots4,
                       const float* __restrict__ op_raw,
                       const float4* __restrict__ shs4,
                       const float* __restrict__ view,
                       const float* __restrict__ proj,
                       const float* __restrict__ campos)
{
    int n = blockIdx.x * blockDim.x + threadIdx.x;
    if (n >= NG) return;

    // ---- wide loads first (maximize MLP) ----
    float4 q4 = rots4[n];
    float sh[48];
    {
        const float4* sb = shs4 + n * 12;
        #pragma unroll
        for (int i = 0; i < 12; i++) {
            float4 v4 = sb[i];
            sh[4*i+0] = v4.x; sh[4*i+1] = v4.y; sh[4*i+2] = v4.z; sh[4*i+3] = v4.w;
        }
    }
    float mx = __ldg(means + 3*n + 0), my = __ldg(means + 3*n + 1), mz = __ldg(means + 3*n + 2);
    float sx = __expf(__ldg(scales_raw + 3*n + 0));
    float sy = __expf(__ldg(scales_raw + 3*n + 1));
    float sz = __expf(__ldg(scales_raw + 3*n + 2));
    float opr = __ldg(op_raw + n);

    float qr = q4.x, qx = q4.y, qy = q4.z, qz = q4.w;
    float qn = rsqrtf(qr*qr + qx*qx + qy*qy + qz*qz);
    qr *= qn; qx *= qn; qy *= qn; qz *= qn;

    float R00 = 1.f - 2.f*(qy*qy + qz*qz);
    float R01 = 2.f*(qx*qy - qr*qz);
    float R02 = 2.f*(qx*qz + qr*qy);
    float R10 = 2.f*(qx*qy + qr*qz);
    float R11 = 1.f - 2.f*(qx*qx + qz*qz);
    float R12 = 2.f*(qy*qz - qr*qx);
    float R20 = 2.f*(qx*qz - qr*qy);
    float R21 = 2.f*(qy*qz + qr*qx);
    float R22 = 1.f - 2.f*(qx*qx + qy*qy);

    float L00 = R00*sx, L01 = R01*sy, L02 = R02*sz;
    float L10 = R10*sx, L11 = R11*sy, L12 = R12*sz;
    float L20 = R20*sx, L21 = R21*sy, L22 = R22*sz;
    float S00 = L00*L00 + L01*L01 + L02*L02;
    float S01 = L00*L10 + L01*L11 + L02*L12;
    float S02 = L00*L20 + L01*L21 + L02*L22;
    float S11 = L10*L10 + L11*L11 + L12*L12;
    float S12 = L10*L20 + L11*L21 + L12*L22;
    float S22 = L20*L20 + L21*L21 + L22*L22;

    float v[16], p[16];
    #pragma unroll
    for (int i = 0; i < 16; i++) { v[i] = view[i]; p[i] = proj[i]; }

    float pv0 = v[0]*mx + v[1]*my + v[2]*mz + v[3];
    float pv1 = v[4]*mx + v[5]*my + v[6]*mz + v[7];
    float pv2 = v[8]*mx + v[9]*my + v[10]*mz + v[11];
    float depth = pv2;

    float ph0 = p[0]*mx + p[1]*my + p[2]*mz + p[3];
    float ph1 = p[4]*mx + p[5]*my + p[6]*mz + p[7];
    float ph3 = p[12]*mx + p[13]*my + p[14]*mz + p[15];
    float pw  = 1.f / (ph3 + 1e-7f);
    float mxs = ((ph0*pw + 1.f) * (float)IW - 1.f) * 0.5f;
    float mys = ((ph1*pw + 1.f) * (float)IH - 1.f) * 0.5f;

    float tz = depth;
    float invtz = 1.f / tz;
    float txc = fminf(fmaxf(pv0*invtz, -LIMV), LIMV) * tz;
    float tyc = fminf(fmaxf(pv1*invtz, -LIMV), LIMV) * tz;
    float J00 = FXY * invtz;
    float J02 = -FXY * txc * invtz * invtz;
    float J11 = FXY * invtz;
    float J12 = -FXY * tyc * invtz * invtz;

    float M00 = J00*v[0] + J02*v[8];
    float M01 = J00*v[1] + J02*v[9];
    float M02 = J00*v[2] + J02*v[10];
    float M10 = J11*v[4] + J12*v[8];
    float M11 = J11*v[5] + J12*v[9];
    float M12 = J11*v[6] + J12*v[10];

    float t00 = M00*S00 + M01*S01 + M02*S02;
    float t01 = M00*S01 + M01*S11 + M02*S12;
    float t02 = M00*S02 + M01*S12 + M02*S22;
    float t10 = M10*S00 + M11*S01 + M12*S02;
    float t11 = M10*S01 + M11*S11 + M12*S12;
    float t12 = M10*S02 + M11*S12 + M12*S22;
    float cov00 = t00*M00 + t01*M01 + t02*M02;
    float cov01 = t00*M10 + t01*M11 + t02*M12;
    float cov11 = t10*M10 + t11*M11 + t12*M12;

    float a  = cov00 + 0.3f;
    float bb = cov01;
    float c  = cov11 + 0.3f;
    float det = a*c - bb*bb;

    float op = 1.f / (1.f + __expf(-opr));

    float dx0 = mx - campos[0], dy0 = my - campos[1], dz0 = mz - campos[2];
    float rn = rsqrtf(dx0*dx0 + dy0*dy0 + dz0*dz0);
    float x = dx0*rn, y = dy0*rn, z = dz0*rn;
    float xx = x*x, yy = y*y, zz = z*z;
    float xy = x*y, yz = y*z, xz = x*z;

    const float C0f = 0.28209479177387814f;
    const float C1f = 0.4886025119029199f;
    const float C2f0 = 1.0925484305920792f, C2f1 = -1.0925484305920792f;
    const float C2f2 = 0.31539156525252005f, C2f3 = -1.0925484305920792f;
    const float C2f4 = 0.5462742152960396f;
    const float C3f0 = -0.5900435899266435f, C3f1 = 2.890611442640554f;
    const float C3f2 = -0.4570457994644658f, C3f3 = 0.3731763325901154f;
    const float C3f4 = -0.4570457994644658f, C3f5 = 1.445305721320277f;
    const float C3f6 = -0.5900435899266435f;

    // basis functions shared across channels
    float b1 = -C1f*y, b2 = C1f*z, b3 = -C1f*x;
    float b4 = C2f0*xy, b5 = C2f1*yz, b6 = C2f2*(2.f*zz - xx - yy);
    float b7 = C2f3*xz, b8 = C2f4*(xx - yy);
    float b9  = C3f0*y*(3.f*xx - yy);
    float b10 = C3f1*xy*z;
    float b11 = C3f2*y*(4.f*zz - xx - yy);
    float b12 = C3f3*z*(2.f*zz - 3.f*xx - 3.f*yy);
    float b13 = C3f4*x*(4.f*zz - xx - yy);
    float b14 = C3f5*z*(xx - yy);
    float b15 = C3f6*x*(xx - 3.f*yy);

    float col[3];
    #pragma unroll
    for (int ch = 0; ch < 3; ch++) {
        float res = C0f*sh[0+ch]
                  + b1*sh[3+ch]  + b2*sh[6+ch]  + b3*sh[9+ch]
                  + b4*sh[12+ch] + b5*sh[15+ch] + b6*sh[18+ch]
                  + b7*sh[21+ch] + b8*sh[24+ch]
                  + b9*sh[27+ch] + b10*sh[30+ch] + b11*sh[33+ch]
                  + b12*sh[36+ch] + b13*sh[39+ch] + b14*sh[42+ch] + b15*sh[45+ch];
        col[ch] = fmaxf(res + 0.5f, 0.f);
    }

    bool valid = (depth > 0.2f) && (det > 0.f);
    float A, B, C, pth;
    float bxmin = 1e9f, bxmax = -1e9f, bymin = 1e9f, bymax = -1e9f;
    float q2 = __logf(255.f * op) + 0.02f;
    if (valid && q2 > 0.f) {
        float invdet = 1.f / det;
        A = c * invdet;
        B = -bb * invdet;
        C = a * invdet;
        pth = -q2;
        float dxm = sqrtf(2.f * q2 * a) + 1e-3f;
        float dym = sqrtf(2.f * q2 * c) + 1e-3f;
        bxmin = mxs - dxm; bxmax = mxs + dxm;
        bymin = mys - dym; bymax = mys + dym;
    } else {
        mxs = 0.f; mys = 0.f;
        A = 0.f; B = 0.f; C = 0.f;
        op = 0.f;
        pth = 1.0f;
    }

    g_p0[n] = make_float4(mxs, mys, A, B);
    g_p1[n] = make_float4(C, op, col[0], col[1]);
    g_p2[n] = make_float2(col[2], pth);
    g_p3[n] = make_float4(bxmin, bxmax, bymin, bymax);

    unsigned int b32 = __float_as_uint(depth);
    b32 ^= (b32 >> 31) ? 0xFFFFFFFFu : 0x80000000u;
    g_key[n] = ((u64)b32 << 32) | (unsigned int)n;
}

// ---------------- 2) fused rank sort + scatter (atomic-free, fence-free) ----------------
__global__ __launch_bounds__(256)
void rank_scatter_kernel()
{
    __shared__ u64 keys[2048];   // 16 KB staging, two halves
    int t = threadIdx.x;
    int blk = blockIdx.x;
    int elem  = blk * 32 + (t >> 3);
    int slice = t & 7;
    u64 myk = g_key[elem];
    int cnt = 0;
    #pragma unroll
    for (int st = 0; st < 2; st++) {
        #pragma unroll
        for (int u = 0; u < 8; u++)
            keys[u*256 + t] = g_key[st*2048 + u*256 + t];
        __syncthreads();
        int kb = slice * 256;
        #pragma unroll 8
        for (int j = 0; j < 256; j++)
            cnt += (keys[kb + j] < myk) ? 1 : 0;
        __syncthreads();
    }
    cnt += __shfl_xor_sync(0xffffffffu, cnt, 1);
    cnt += __shfl_xor_sync(0xffffffffu, cnt, 2);
    cnt += __shfl_xor_sync(0xffffffffu, cnt, 4);
    if (slice == 0) {
        g_s0[cnt] = g_p0[elem];
        g_s1[cnt] = g_p1[elem];
        g_s2[cnt] = g_p2[elem];
        g_s3[cnt] = g_p3[elem];
    }
}

// ---------------- 3) tiled render (no fences, partials only) ----------------
__global__ __launch_bounds__(256)
void render_tile_kernel()
{
    __shared__ float4 c0[256];
    __shared__ float4 c1[256];
    __shared__ float2 c2[256];
    __shared__ int wcnt[8];

    int tile  = blockIdx.x;
    int chunk = blockIdx.y;
    int t = threadIdx.x;
    int w = t >> 5, lane = t & 31;

    float tx0 = (float)((tile % 6) * 16);
    float ty0 = (float)((tile / 6) * 16);
    float tx1 = tx0 + 15.f;
    float ty1 = ty0 + 15.f;
    float px = tx0 + (float)(t & 15);
    float py = ty0 + (float)(t >> 4);

    float T = 1.f, cr = 0.f, cg = 0.f, cb = 0.f;

    int gi = chunk * RCHSZ + t;
    float4 bbx = g_s3[gi];
    bool hit = (bbx.x <= tx1) && (bbx.y >= tx0) && (bbx.z <= ty1) && (bbx.w >= ty0);
    unsigned int bal = __ballot_sync(0xffffffffu, hit);
    if (lane == 0) wcnt[w] = __popc(bal);
    __syncthreads();

    int off = 0, m = 0;
    #pragma unroll
    for (int i = 0; i < 8; i++) {
        int cnt = wcnt[i];
        if (i < w) off += cnt;
        m += cnt;
    }
    if (hit) {
        int pos = off + __popc(bal & ((1u << lane) - 1u));
        c0[pos] = g_s0[gi];
        c1[pos] = g_s1[gi];
        c2[pos] = g_s2[gi];
    }
    __syncthreads();

    for (int i = 0; i < m; i++) {
        float4 a0 = c0[i];
        float2 a2 = c2[i];
        float dx = px - a0.x;
        float dy = py - a0.y;
        float4 a1 = c1[i];
        float power = -0.5f * (a0.z*dx*dx + a1.x*dy*dy) - a0.w*dx*dy;
        if (power < a2.y) continue;          // conic pos-def => power<=0 always
        float alpha = fminf(0.99f, a1.y * __expf(power));
        if (alpha < INV255) continue;
        float wgt = alpha * T;
        cr = fmaf(wgt, a1.z, cr);
        cg = fmaf(wgt, a1.w, cg);
        cb = fmaf(wgt, a2.x, cb);
        T *= (1.f - alpha);
    }

    int pbase = (chunk * 4) * (NTILE * 256) + tile * 256 + t;
    g_partial[pbase]                 = cr;
    g_partial[pbase + NTILE*256]     = cg;
    g_partial[pbase + 2*NTILE*256]   = cb;
    g_partial[pbase + 3*NTILE*256]   = T;
}

// ---------------- 4) combine chunks + background ----------------
__global__ __launch_bounds__(128)
void combine_kernel(const float* __restrict__ bg, float* __restrict__ out)
{
    int tp = blockIdx.x * 128 + threadIdx.x;   // 0..9215 (tile*256 + t)
    int tile = tp >> 8;
    int t    = tp & 255;
    float bg0 = __ldg(bg + 0), bg1 = __ldg(bg + 1), bg2 = __ldg(bg + 2);
    float T = 1.f, r = 0.f, g = 0.f, b = 0.f;
    #pragma unroll
    for (int k = 0; k < RCH; k++) {
        int pb = (k * 4) * (NTILE * 256) + tp;
        r += T * g_partial[pb];
        g += T * g_partial[pb + NTILE*256];
        b += T * g_partial[pb + 2*NTILE*256];
        T *= g_partial[pb + 3*NTILE*256];
    }
    int pix = ((tile / 6) * 16 + (t >> 4)) * IW + (tile % 6) * 16 + (t & 15);
    out[pix]          = r + T * bg0;
    out[NPIX + pix]   = g + T * bg1;
    out[2*NPIX + pix] = b + T * bg2;
}

extern "C" void kernel_launch(void* const* d_in, const int* in_sizes, int n_in,
                              void* d_out, int out_size)
{
    const float* means      = (const float*)d_in[0];
    const float* scales_raw = (const float*)d_in[1];
    const float* rots       = (const float*)d_in[2];
    const float* op_raw     = (const float*)d_in[3];
    const float* shs        = (const float*)d_in[4];
    const float* view       = (const float*)d_in[5];
    const float* proj       = (const float*)d_in[6];
    const float* campos     = (const float*)d_in[7];
    const float* bg         = (const float*)d_in[8];
    float* out = (float*)d_out;

    preprocess_kernel<<<32, 128>>>(means, scales_raw, (const float4*)rots, op_raw,
                                   (const float4*)shs, view, proj, campos);
    rank_scatter_kernel<<<128, 256>>>();
    render_tile_kernel<<<dim3(NTILE, RCH), 256>>>();
    combine_kernel<<<NPIX/128, 128>>>(bg, out);
}

// round 9
// speedup vs baseline: 3.3760x; 2.0108x over previous
#include <cuda_runtime.h>
#include <math.h>

#define NG    4096
#define IW    96
#define IH    96
#define NPIX  (IW*IH)
#define NTILE 36            // 6x6 tiles of 16x16
#define RCH   8             // depth chunks for render parallelism
#define RCHSZ (NG/RCH)      // 512
#define TANFOV 0.36502849177392513f
#define LIMV   (1.3f*TANFOV)
#define FXY    (96.0f/(2.0f*TANFOV))
#define INV255 0.0039215686274509803f

typedef unsigned long long u64;

// ---------------- scratch (no allocations allowed) ----------------
__device__ float4 g_p0[NG], g_p1[NG], g_p3[NG];   // unsorted packed params (+bbox)
__device__ float2 g_p2[NG];
__device__ u64    g_key[NG];
__device__ int    g_rank[NG];
__device__ int    g_tilecnt[NTILE];
__device__ float4 g_s0[NG], g_s1[NG], g_s3[NG];   // sorted
__device__ float2 g_s2[NG];
__device__ float  g_partial[RCH * 4 * NTILE * 256];

// ---------------- 1) per-gaussian preprocess (vectorized loads) ----------------
__global__ __launch_bounds__(128)
void preprocess_kernel(const float* __restrict__ means,
                       const float* __restrict__ scales_raw,
                       const float4* __restrict__ rots4,
                       const float* __restrict__ op_raw,
                       const float4* __restrict__ shs4,
                       const float* __restrict__ view,
                       const float* __restrict__ proj,
                       const float* __restrict__ campos)
{
    int n = blockIdx.x * blockDim.x + threadIdx.x;
    if (n >= NG) return;

    // per-replay state reset (stream order guarantees this runs first)
    g_rank[n] = 0;
    if (n < NTILE) g_tilecnt[n] = 0;

    // ---- wide loads first (maximize MLP) ----
    float4 q4 = rots4[n];
    float sh[48];
    {
        const float4* sb = shs4 + n * 12;
        #pragma unroll
        for (int i = 0; i < 12; i++) {
            float4 v4 = sb[i];
            sh[4*i+0] = v4.x; sh[4*i+1] = v4.y; sh[4*i+2] = v4.z; sh[4*i+3] = v4.w;
        }
    }
    float mx = __ldg(means + 3*n + 0), my = __ldg(means + 3*n + 1), mz = __ldg(means + 3*n + 2);
    float sx = __expf(__ldg(scales_raw + 3*n + 0));
    float sy = __expf(__ldg(scales_raw + 3*n + 1));
    float sz = __expf(__ldg(scales_raw + 3*n + 2));
    float opr = __ldg(op_raw + n);

    float qr = q4.x, qx = q4.y, qy = q4.z, qz = q4.w;
    float qn = rsqrtf(qr*qr + qx*qx + qy*qy + qz*qz);
    qr *= qn; qx *= qn; qy *= qn; qz *= qn;

    float R00 = 1.f - 2.f*(qy*qy + qz*qz);
    float R01 = 2.f*(qx*qy - qr*qz);
    float R02 = 2.f*(qx*qz + qr*qy);
    float R10 = 2.f*(qx*qy + qr*qz);
    float R11 = 1.f - 2.f*(qx*qx + qz*qz);
    float R12 = 2.f*(qy*qz - qr*qx);
    float R20 = 2.f*(qx*qz - qr*qy);
    float R21 = 2.f*(qy*qz + qr*qx);
    float R22 = 1.f - 2.f*(qx*qx + qy*qy);

    float L00 = R00*sx, L01 = R01*sy, L02 = R02*sz;
    float L10 = R10*sx, L11 = R11*sy, L12 = R12*sz;
    float L20 = R20*sx, L21 = R21*sy, L22 = R22*sz;
    float S00 = L00*L00 + L01*L01 + L02*L02;
    float S01 = L00*L10 + L01*L11 + L02*L12;
    float S02 = L00*L20 + L01*L21 + L02*L22;
    float S11 = L10*L10 + L11*L11 + L12*L12;
    float S12 = L10*L20 + L11*L21 + L12*L22;
    float S22 = L20*L20 + L21*L21 + L22*L22;

    float v[16], p[16];
    #pragma unroll
    for (int i = 0; i < 16; i++) { v[i] = view[i]; p[i] = proj[i]; }

    float pv0 = v[0]*mx + v[1]*my + v[2]*mz + v[3];
    float pv1 = v[4]*mx + v[5]*my + v[6]*mz + v[7];
    float pv2 = v[8]*mx + v[9]*my + v[10]*mz + v[11];
    float depth = pv2;

    float ph0 = p[0]*mx + p[1]*my + p[2]*mz + p[3];
    float ph1 = p[4]*mx + p[5]*my + p[6]*mz + p[7];
    float ph3 = p[12]*mx + p[13]*my + p[14]*mz + p[15];
    float pw  = 1.f / (ph3 + 1e-7f);
    float mxs = ((ph0*pw + 1.f) * (float)IW - 1.f) * 0.5f;
    float mys = ((ph1*pw + 1.f) * (float)IH - 1.f) * 0.5f;

    float tz = depth;
    float invtz = 1.f / tz;
    float txc = fminf(fmaxf(pv0*invtz, -LIMV), LIMV) * tz;
    float tyc = fminf(fmaxf(pv1*invtz, -LIMV), LIMV) * tz;
    float J00 = FXY * invtz;
    float J02 = -FXY * txc * invtz * invtz;
    float J11 = FXY * invtz;
    float J12 = -FXY * tyc * invtz * invtz;

    float M00 = J00*v[0] + J02*v[8];
    float M01 = J00*v[1] + J02*v[9];
    float M02 = J00*v[2] + J02*v[10];
    float M10 = J11*v[4] + J12*v[8];
    float M11 = J11*v[5] + J12*v[9];
    float M12 = J11*v[6] + J12*v[10];

    float t00 = M00*S00 + M01*S01 + M02*S02;
    float t01 = M00*S01 + M01*S11 + M02*S12;
    float t02 = M00*S02 + M01*S12 + M02*S22;
    float t10 = M10*S00 + M11*S01 + M12*S02;
    float t11 = M10*S01 + M11*S11 + M12*S12;
    float t12 = M10*S02 + M11*S12 + M12*S22;
    float cov00 = t00*M00 + t01*M01 + t02*M02;
    float cov01 = t00*M10 + t01*M11 + t02*M12;
    float cov11 = t10*M10 + t11*M11 + t12*M12;

    float a  = cov00 + 0.3f;
    float bb = cov01;
    float c  = cov11 + 0.3f;
    float det = a*c - bb*bb;

    float op = 1.f / (1.f + __expf(-opr));

    float dx0 = mx - campos[0], dy0 = my - campos[1], dz0 = mz - campos[2];
    float rn = rsqrtf(dx0*dx0 + dy0*dy0 + dz0*dz0);
    float x = dx0*rn, y = dy0*rn, z = dz0*rn;
    float xx = x*x, yy = y*y, zz = z*z;
    float xy = x*y, yz = y*z, xz = x*z;

    const float C0f = 0.28209479177387814f;
    const float C1f = 0.4886025119029199f;
    const float C2f0 = 1.0925484305920792f, C2f1 = -1.0925484305920792f;
    const float C2f2 = 0.31539156525252005f, C2f3 = -1.0925484305920792f;
    const float C2f4 = 0.5462742152960396f;
    const float C3f0 = -0.5900435899266435f, C3f1 = 2.890611442640554f;
    const float C3f2 = -0.4570457994644658f, C3f3 = 0.3731763325901154f;
    const float C3f4 = -0.4570457994644658f, C3f5 = 1.445305721320277f;
    const float C3f6 = -0.5900435899266435f;

    float b1 = -C1f*y, b2 = C1f*z, b3 = -C1f*x;
    float b4 = C2f0*xy, b5 = C2f1*yz, b6 = C2f2*(2.f*zz - xx - yy);
    float b7 = C2f3*xz, b8 = C2f4*(xx - yy);
    float b9  = C3f0*y*(3.f*xx - yy);
    float b10 = C3f1*xy*z;
    float b11 = C3f2*y*(4.f*zz - xx - yy);
    float b12 = C3f3*z*(2.f*zz - 3.f*xx - 3.f*yy);
    float b13 = C3f4*x*(4.f*zz - xx - yy);
    float b14 = C3f5*z*(xx - yy);
    float b15 = C3f6*x*(xx - 3.f*yy);

    float col[3];
    #pragma unroll
    for (int ch = 0; ch < 3; ch++) {
        float res = C0f*sh[0+ch]
                  + b1*sh[3+ch]  + b2*sh[6+ch]  + b3*sh[9+ch]
                  + b4*sh[12+ch] + b5*sh[15+ch] + b6*sh[18+ch]
                  + b7*sh[21+ch] + b8*sh[24+ch]
                  + b9*sh[27+ch] + b10*sh[30+ch] + b11*sh[33+ch]
                  + b12*sh[36+ch] + b13*sh[39+ch] + b14*sh[42+ch] + b15*sh[45+ch];
        col[ch] = fmaxf(res + 0.5f, 0.f);
    }

    bool valid = (depth > 0.2f) && (det > 0.f);
    float A, B, C, pth;
    float bxmin = 1e9f, bxmax = -1e9f, bymin = 1e9f, bymax = -1e9f;
    float q2 = __logf(255.f * op) + 0.02f;
    if (valid && q2 > 0.f) {
        float invdet = 1.f / det;
        A = c * invdet;
        B = -bb * invdet;
        C = a * invdet;
        pth = -q2;
        float dxm = sqrtf(2.f * q2 * a) + 1e-3f;
        float dym = sqrtf(2.f * q2 * c) + 1e-3f;
        bxmin = mxs - dxm; bxmax = mxs + dxm;
        bymin = mys - dym; bymax = mys + dym;
    } else {
        mxs = 0.f; mys = 0.f;
        A = 0.f; B = 0.f; C = 0.f;
        op = 0.f;
        pth = 1.0f;
    }

    g_p0[n] = make_float4(mxs, mys, A, B);
    g_p1[n] = make_float4(C, op, col[0], col[1]);
    g_p2[n] = make_float2(col[2], pth);
    g_p3[n] = make_float4(bxmin, bxmax, bymin, bymax);

    unsigned int b32 = __float_as_uint(depth);
    b32 ^= (b32 >> 31) ? 0xFFFFFFFFu : 0x80000000u;
    g_key[n] = ((u64)b32 << 32) | (unsigned int)n;
}

// ---------------- 2) full-chip rank sort ----------------
#define KCH 512
__global__ __launch_bounds__(256)
void rank_kernel()
{
    __shared__ u64 sk[KCH];
    int t = threadIdx.x;
    int e = blockIdx.x * 256 + t;
    int kbase = blockIdx.y * KCH;

    sk[t]       = g_key[kbase + t];
    sk[t + 256] = g_key[kbase + 256 + t];
    u64 myk = g_key[e];
    __syncthreads();

    int cnt = 0;
    #pragma unroll 8
    for (int i = 0; i < KCH; i++)
        cnt += (sk[i] < myk) ? 1 : 0;

    atomicAdd(&g_rank[e], cnt);
}

// ---------------- 3) scatter into sorted order ----------------
__global__ __launch_bounds__(256)
void scatter_kernel()
{
    int i = blockIdx.x * blockDim.x + threadIdx.x;
    int r = g_rank[i];
    g_s0[r] = g_p0[i];
    g_s1[r] = g_p1[i];
    g_s2[r] = g_p2[i];
    g_s3[r] = g_p3[i];
}

// ---------------- 4) tiled render + fused combine ----------------
__global__ __launch_bounds__(256)
void render_tile_kernel(const float* __restrict__ bg, float* __restrict__ out)
{
    __shared__ float4 c0[256];
    __shared__ float4 c1[256];
    __shared__ float2 c2[256];
    __shared__ int wcnt[8];
    __shared__ int sdone;

    int tile  = blockIdx.x;
    int chunk = blockIdx.y;
    int t = threadIdx.x;
    int w = t >> 5, lane = t & 31;

    float tx0 = (float)((tile % 6) * 16);
    float ty0 = (float)((tile / 6) * 16);
    float tx1 = tx0 + 15.f;
    float ty1 = ty0 + 15.f;
    float px = tx0 + (float)(t & 15);
    float py = ty0 + (float)(t >> 4);

    float T = 1.f, cr = 0.f, cg = 0.f, cb = 0.f;
    int base = chunk * RCHSZ;

    for (int g0 = 0; g0 < RCHSZ; g0 += 256) {
        int gi = base + g0 + t;
        float4 bbx = g_s3[gi];
        bool hit = (bbx.x <= tx1) && (bbx.y >= tx0) && (bbx.z <= ty1) && (bbx.w >= ty0);
        unsigned int bal = __ballot_sync(0xffffffffu, hit);
        if (lane == 0) wcnt[w] = __popc(bal);
        __syncthreads();

        int off = 0, m = 0;
        #pragma unroll
        for (int i = 0; i < 8; i++) {
            int cnt = wcnt[i];
            if (i < w) off += cnt;
            m += cnt;
        }
        if (hit) {
            int pos = off + __popc(bal & ((1u << lane) - 1u));
            c0[pos] = g_s0[gi];
            c1[pos] = g_s1[gi];
            c2[pos] = g_s2[gi];
        }
        __syncthreads();

        for (int i = 0; i < m; i++) {
            float4 a0 = c0[i];
            float2 a2 = c2[i];
            float dx = px - a0.x;
            float dy = py - a0.y;
            float4 a1 = c1[i];
            float power = -0.5f * (a0.z*dx*dx + a1.x*dy*dy) - a0.w*dx*dy;
            if (power < a2.y) continue;
            float alpha = fminf(0.99f, a1.y * __expf(power));
            if (alpha < INV255) continue;
            float wgt = alpha * T;
            cr = fmaf(wgt, a1.z, cr);
            cg = fmaf(wgt, a1.w, cg);
            cb = fmaf(wgt, a2.x, cb);
            T *= (1.f - alpha);
        }
        __syncthreads();
    }

    int pbase = (chunk * 4) * (NTILE * 256) + tile * 256 + t;
    g_partial[pbase]                 = cr;
    g_partial[pbase + NTILE*256]     = cg;
    g_partial[pbase + 2*NTILE*256]   = cb;
    g_partial[pbase + 3*NTILE*256]   = T;

    // last block for this tile folds the chunks (classic threadfence reduction)
    __threadfence();
    if (t == 0) sdone = atomicAdd(&g_tilecnt[tile], 1);
    __syncthreads();
    if (sdone == RCH - 1) {
        __threadfence();
        float Tt = 1.f, r = 0.f, g = 0.f, b = 0.f;
        #pragma unroll
        for (int k = 0; k < RCH; k++) {
            int pb = (k * 4) * (NTILE * 256) + tile * 256 + t;
            r += Tt * g_partial[pb];
            g += Tt * g_partial[pb + NTILE*256];
            b += Tt * g_partial[pb + 2*NTILE*256];
            Tt *= g_partial[pb + 3*NTILE*256];
        }
        int pix = ((tile / 6) * 16 + (t >> 4)) * IW + (tile % 6) * 16 + (t & 15);
        out[pix]          = r + Tt * bg[0];
        out[NPIX + pix]   = g + Tt * bg[1];
        out[2*NPIX + pix] = b + Tt * bg[2];
    }
}

extern "C" void kernel_launch(void* const* d_in, const int* in_sizes, int n_in,
                              void* d_out, int out_size)
{
    const float* means      = (const float*)d_in[0];
    const float* scales_raw = (const float*)d_in[1];
    const float* rots       = (const float*)d_in[2];
    const float* op_raw     = (const float*)d_in[3];
    const float* shs        = (const float*)d_in[4];
    const float* view       = (const float*)d_in[5];
    const float* proj       = (const float*)d_in[6];
    const float* campos     = (const float*)d_in[7];
    const float* bg         = (const float*)d_in[8];
    float* out = (float*)d_out;

    preprocess_kernel<<<32, 128>>>(means, scales_raw, (const float4*)rots, op_raw,
                                   (const float4*)shs, view, proj, campos);
    rank_kernel<<<dim3(NG/256, NG/KCH), 256>>>();
    scatter_kernel<<<NG/256, 256>>>();
    render_tile_kernel<<<dim3(NTILE, RCH), 256>>>(bg, out);
}

// round 10
// speedup vs baseline: 3.6468x; 1.0802x over previous
#include <cuda_runtime.h>
#include <math.h>

#define NG    4096
#define IW    96
#define IH    96
#define NPIX  (IW*IH)
#define NTILE 36            // 6x6 tiles of 16x16
#define RCH   16            // depth chunks for render parallelism
#define RCHSZ (NG/RCH)      // 256
#define TANFOV 0.36502849177392513f
#define LIMV   (1.3f*TANFOV)
#define FXY    (96.0f/(2.0f*TANFOV))
#define INV255 0.0039215686274509803f

typedef unsigned long long u64;

// ---------------- scratch (no allocations allowed) ----------------
__device__ float4 g_p0[NG], g_p1[NG], g_p3[NG];   // unsorted packed params (+bbox)
__device__ float2 g_p2[NG];
__device__ u64    g_key[NG];
__device__ int    g_rank[NG];
__device__ int    g_tilecnt[NTILE];
__device__ float4 g_s0[NG], g_s1[NG], g_s3[NG];   // sorted
__device__ float2 g_s2[NG];
__device__ float  g_partial[RCH * 4 * NTILE * 256];

// ---------------- 1) per-gaussian preprocess (vectorized loads) ----------------
__global__ __launch_bounds__(128)
void preprocess_kernel(const float* __restrict__ means,
                       const float* __restrict__ scales_raw,
                       const float4* __restrict__ rots4,
                       const float* __restrict__ op_raw,
                       const float4* __restrict__ shs4,
                       const float* __restrict__ view,
                       const float* __restrict__ proj,
                       const float* __restrict__ campos)
{
    int n = blockIdx.x * blockDim.x + threadIdx.x;
    if (n >= NG) return;

    // per-replay state reset (stream order guarantees this runs first)
    g_rank[n] = 0;
    if (n < NTILE) g_tilecnt[n] = 0;

    // ---- wide loads first (maximize MLP) ----
    float4 q4 = rots4[n];
    float sh[48];
    {
        const float4* sb = shs4 + n * 12;
        #pragma unroll
        for (int i = 0; i < 12; i++) {
            float4 v4 = sb[i];
            sh[4*i+0] = v4.x; sh[4*i+1] = v4.y; sh[4*i+2] = v4.z; sh[4*i+3] = v4.w;
        }
    }
    float mx = __ldg(means + 3*n + 0), my = __ldg(means + 3*n + 1), mz = __ldg(means + 3*n + 2);
    float sx = __expf(__ldg(scales_raw + 3*n + 0));
    float sy = __expf(__ldg(scales_raw + 3*n + 1));
    float sz = __expf(__ldg(scales_raw + 3*n + 2));
    float opr = __ldg(op_raw + n);

    float qr = q4.x, qx = q4.y, qy = q4.z, qz = q4.w;
    float qn = rsqrtf(qr*qr + qx*qx + qy*qy + qz*qz);
    qr *= qn; qx *= qn; qy *= qn; qz *= qn;

    float R00 = 1.f - 2.f*(qy*qy + qz*qz);
    float R01 = 2.f*(qx*qy - qr*qz);
    float R02 = 2.f*(qx*qz + qr*qy);
    float R10 = 2.f*(qx*qy + qr*qz);
    float R11 = 1.f - 2.f*(qx*qx + qz*qz);
    float R12 = 2.f*(qy*qz - qr*qx);
    float R20 = 2.f*(qx*qz - qr*qy);
    float R21 = 2.f*(qy*qz + qr*qx);
    float R22 = 1.f - 2.f*(qx*qx + qy*qy);

    float L00 = R00*sx, L01 = R01*sy, L02 = R02*sz;
    float L10 = R10*sx, L11 = R11*sy, L12 = R12*sz;
    float L20 = R20*sx, L21 = R21*sy, L22 = R22*sz;
    float S00 = L00*L00 + L01*L01 + L02*L02;
    float S01 = L00*L10 + L01*L11 + L02*L12;
    float S02 = L00*L20 + L01*L21 + L02*L22;
    float S11 = L10*L10 + L11*L11 + L12*L12;
    float S12 = L10*L20 + L11*L21 + L12*L22;
    float S22 = L20*L20 + L21*L21 + L22*L22;

    float v[16], p[16];
    #pragma unroll
    for (int i = 0; i < 16; i++) { v[i] = view[i]; p[i] = proj[i]; }

    float pv0 = v[0]*mx + v[1]*my + v[2]*mz + v[3];
    float pv1 = v[4]*mx + v[5]*my + v[6]*mz + v[7];
    float pv2 = v[8]*mx + v[9]*my + v[10]*mz + v[11];
    float depth = pv2;

    float ph0 = p[0]*mx + p[1]*my + p[2]*mz + p[3];
    float ph1 = p[4]*mx + p[5]*my + p[6]*mz + p[7];
    float ph3 = p[12]*mx + p[13]*my + p[14]*mz + p[15];
    float pw  = 1.f / (ph3 + 1e-7f);
    float mxs = ((ph0*pw + 1.f) * (float)IW - 1.f) * 0.5f;
    float mys = ((ph1*pw + 1.f) * (float)IH - 1.f) * 0.5f;

    float tz = depth;
    float invtz = 1.f / tz;
    float txc = fminf(fmaxf(pv0*invtz, -LIMV), LIMV) * tz;
    float tyc = fminf(fmaxf(pv1*invtz, -LIMV), LIMV) * tz;
    float J00 = FXY * invtz;
    float J02 = -FXY * txc * invtz * invtz;
    float J11 = FXY * invtz;
    float J12 = -FXY * tyc * invtz * invtz;

    float M00 = J00*v[0] + J02*v[8];
    float M01 = J00*v[1] + J02*v[9];
    float M02 = J00*v[2] + J02*v[10];
    float M10 = J11*v[4] + J12*v[8];
    float M11 = J11*v[5] + J12*v[9];
    float M12 = J11*v[6] + J12*v[10];

    float t00 = M00*S00 + M01*S01 + M02*S02;
    float t01 = M00*S01 + M01*S11 + M02*S12;
    float t02 = M00*S02 + M01*S12 + M02*S22;
    float t10 = M10*S00 + M11*S01 + M12*S02;
    float t11 = M10*S01 + M11*S11 + M12*S12;
    float t12 = M10*S02 + M11*S12 + M12*S22;
    float cov00 = t00*M00 + t01*M01 + t02*M02;
    float cov01 = t00*M10 + t01*M11 + t02*M12;
    float cov11 = t10*M10 + t11*M11 + t12*M12;

    float a  = cov00 + 0.3f;
    float bb = cov01;
    float c  = cov11 + 0.3f;
    float det = a*c - bb*bb;

    float op = 1.f / (1.f + __expf(-opr));

    float dx0 = mx - campos[0], dy0 = my - campos[1], dz0 = mz - campos[2];
    float rn = rsqrtf(dx0*dx0 + dy0*dy0 + dz0*dz0);
    float x = dx0*rn, y = dy0*rn, z = dz0*rn;
    float xx = x*x, yy = y*y, zz = z*z;
    float xy = x*y, yz = y*z, xz = x*z;

    const float C0f = 0.28209479177387814f;
    const float C1f = 0.4886025119029199f;
    const float C2f0 = 1.0925484305920792f, C2f1 = -1.0925484305920792f;
    const float C2f2 = 0.31539156525252005f, C2f3 = -1.0925484305920792f;
    const float C2f4 = 0.5462742152960396f;
    const float C3f0 = -0.5900435899266435f, C3f1 = 2.890611442640554f;
    const float C3f2 = -0.4570457994644658f, C3f3 = 0.3731763325901154f;
    const float C3f4 = -0.4570457994644658f, C3f5 = 1.445305721320277f;
    const float C3f6 = -0.5900435899266435f;

    float b1 = -C1f*y, b2 = C1f*z, b3 = -C1f*x;
    float b4 = C2f0*xy, b5 = C2f1*yz, b6 = C2f2*(2.f*zz - xx - yy);
    float b7 = C2f3*xz, b8 = C2f4*(xx - yy);
    float b9  = C3f0*y*(3.f*xx - yy);
    float b10 = C3f1*xy*z;
    float b11 = C3f2*y*(4.f*zz - xx - yy);
    float b12 = C3f3*z*(2.f*zz - 3.f*xx - 3.f*yy);
    float b13 = C3f4*x*(4.f*zz - xx - yy);
    float b14 = C3f5*z*(xx - yy);
    float b15 = C3f6*x*(xx - 3.f*yy);

    float col[3];
    #pragma unroll
    for (int ch = 0; ch < 3; ch++) {
        float res = C0f*sh[0+ch]
                  + b1*sh[3+ch]  + b2*sh[6+ch]  + b3*sh[9+ch]
                  + b4*sh[12+ch] + b5*sh[15+ch] + b6*sh[18+ch]
                  + b7*sh[21+ch] + b8*sh[24+ch]
                  + b9*sh[27+ch] + b10*sh[30+ch] + b11*sh[33+ch]
                  + b12*sh[36+ch] + b13*sh[39+ch] + b14*sh[42+ch] + b15*sh[45+ch];
        col[ch] = fmaxf(res + 0.5f, 0.f);
    }

    bool valid = (depth > 0.2f) && (det > 0.f);
    float A, B, C, pth;
    float bxmin = 1e9f, bxmax = -1e9f, bymin = 1e9f, bymax = -1e9f;
    float q2 = __logf(255.f * op) + 0.02f;
    if (valid && q2 > 0.f) {
        float invdet = 1.f / det;
        A = c * invdet;
        B = -bb * invdet;
        C = a * invdet;
        pth = -q2;
        float dxm = sqrtf(2.f * q2 * a) + 1e-3f;
        float dym = sqrtf(2.f * q2 * c) + 1e-3f;
        bxmin = mxs - dxm; bxmax = mxs + dxm;
        bymin = mys - dym; bymax = mys + dym;
    } else {
        mxs = 0.f; mys = 0.f;
        A = 0.f; B = 0.f; C = 0.f;
        op = 0.f;
        pth = 1.0f;
    }

    g_p0[n] = make_float4(mxs, mys, A, B);
    g_p1[n] = make_float4(C, op, col[0], col[1]);
    g_p2[n] = make_float2(col[2], pth);
    g_p3[n] = make_float4(bxmin, bxmax, bymin, bymax);

    unsigned int b32 = __float_as_uint(depth);
    b32 ^= (b32 >> 31) ? 0xFFFFFFFFu : 0x80000000u;
    g_key[n] = ((u64)b32 << 32) | (unsigned int)n;
}

// ---------------- 2) full-chip rank sort (broadcast LDS, conflict-free) ----------------
#define KCH 512
__global__ __launch_bounds__(256)
void rank_kernel()
{
    __shared__ u64 sk[KCH];
    int t = threadIdx.x;
    int e = blockIdx.x * 256 + t;
    int kbase = blockIdx.y * KCH;

    sk[t]       = g_key[kbase + t];
    sk[t + 256] = g_key[kbase + 256 + t];
    u64 myk = g_key[e];
    __syncthreads();

    int cnt = 0;
    #pragma unroll 8
    for (int i = 0; i < KCH; i++)
        cnt += (sk[i] < myk) ? 1 : 0;

    atomicAdd(&g_rank[e], cnt);
}

// ---------------- 3) scatter into sorted order ----------------
__global__ __launch_bounds__(256)
void scatter_kernel()
{
    int i = blockIdx.x * blockDim.x + threadIdx.x;
    int r = g_rank[i];
    g_s0[r] = g_p0[i];
    g_s1[r] = g_p1[i];
    g_s2[r] = g_p2[i];
    g_s3[r] = g_p3[i];
}

// ---------------- 4) tiled render (single batch) + fused tail combine ----------------
__global__ __launch_bounds__(256)
void render_tile_kernel(const float* __restrict__ bg, float* __restrict__ out)
{
    __shared__ float4 c0[256];
    __shared__ float4 c1[256];
    __shared__ float2 c2[256];
    __shared__ int wcnt[8];
    __shared__ int sdone;

    int tile  = blockIdx.x;
    int chunk = blockIdx.y;
    int t = threadIdx.x;
    int w = t >> 5, lane = t & 31;

    float tx0 = (float)((tile % 6) * 16);
    float ty0 = (float)((tile / 6) * 16);
    float tx1 = tx0 + 15.f;
    float ty1 = ty0 + 15.f;
    float px = tx0 + (float)(t & 15);
    float py = ty0 + (float)(t >> 4);

    float T = 1.f, cr = 0.f, cg = 0.f, cb = 0.f;

    int gi = chunk * RCHSZ + t;
    float4 bbx = g_s3[gi];
    bool hit = (bbx.x <= tx1) && (bbx.y >= tx0) && (bbx.z <= ty1) && (bbx.w >= ty0);
    unsigned int bal = __ballot_sync(0xffffffffu, hit);
    if (lane == 0) wcnt[w] = __popc(bal);
    __syncthreads();

    int off = 0, m = 0;
    #pragma unroll
    for (int i = 0; i < 8; i++) {
        int cnt = wcnt[i];
        if (i < w) off += cnt;
        m += cnt;
    }
    if (hit) {
        int pos = off + __popc(bal & ((1u << lane) - 1u));
        c0[pos] = g_s0[gi];
        c1[pos] = g_s1[gi];
        c2[pos] = g_s2[gi];
    }
    __syncthreads();

    for (int i = 0; i < m; i++) {
        float4 a0 = c0[i];
        float2 a2 = c2[i];
        float dx = px - a0.x;
        float dy = py - a0.y;
        float4 a1 = c1[i];
        float power = -0.5f * (a0.z*dx*dx + a1.x*dy*dy) - a0.w*dx*dy;
        if (power < a2.y) continue;
        float alpha = fminf(0.99f, a1.y * __expf(power));
        if (alpha < INV255) continue;
        float wgt = alpha * T;
        cr = fmaf(wgt, a1.z, cr);
        cg = fmaf(wgt, a1.w, cg);
        cb = fmaf(wgt, a2.x, cb);
        T *= (1.f - alpha);
    }

    int pbase = (chunk * 4) * (NTILE * 256) + tile * 256 + t;
    g_partial[pbase]                 = cr;
    g_partial[pbase + NTILE*256]     = cg;
    g_partial[pbase + 2*NTILE*256]   = cb;
    g_partial[pbase + 3*NTILE*256]   = T;

    // last block for this tile folds the chunks
    __threadfence();
    if (t == 0) sdone = atomicAdd(&g_tilecnt[tile], 1);
    __syncthreads();
    if (sdone == RCH - 1) {
        __threadfence();
        float Tt = 1.f, r = 0.f, g = 0.f, b = 0.f;
        #pragma unroll
        for (int k = 0; k < RCH; k++) {
            int pb = (k * 4) * (NTILE * 256) + tile * 256 + t;
            r += Tt * g_partial[pb];
            g += Tt * g_partial[pb + NTILE*256];
            b += Tt * g_partial[pb + 2*NTILE*256];
            Tt *= g_partial[pb + 3*NTILE*256];
        }
        int pix = ((tile / 6) * 16 + (t >> 4)) * IW + (tile % 6) * 16 + (t & 15);
        out[pix]          = r + Tt * bg[0];
        out[NPIX + pix]   = g + Tt * bg[1];
        out[2*NPIX + pix] = b + Tt * bg[2];
    }
}

extern "C" void kernel_launch(void* const* d_in, const int* in_sizes, int n_in,
                              void* d_out, int out_size)
{
    const float* means      = (const float*)d_in[0];
    const float* scales_raw = (const float*)d_in[1];
    const float* rots       = (const float*)d_in[2];
    const float* op_raw     = (const float*)d_in[3];
    const float* shs        = (const float*)d_in[4];
    const float* view       = (const float*)d_in[5];
    const float* proj       = (const float*)d_in[6];
    const float* campos     = (const float*)d_in[7];
    const float* bg         = (const float*)d_in[8];
    float* out = (float*)d_out;

    preprocess_kernel<<<32, 128>>>(means, scales_raw, (const float4*)rots, op_raw,
                                   (const float4*)shs, view, proj, campos);
    rank_kernel<<<dim3(NG/256, NG/KCH), 256>>>();
    scatter_kernel<<<NG/256, 256>>>();
    render_tile_kernel<<<dim3(NTILE, RCH), 256>>>(bg, out);
}

// round 11
// speedup vs baseline: 3.6658x; 1.0052x over previous
#include <cuda_runtime.h>
#include <math.h>

#define NG    4096
#define IW    96
#define IH    96
#define NPIX  (IW*IH)
#define NTILE 36            // 6x6 tiles of 16x16
#define RCH   32            // depth chunks for render parallelism
#define RCHSZ (NG/RCH)      // 128
#define TANFOV 0.36502849177392513f
#define LIMV   (1.3f*TANFOV)
#define FXY    (96.0f/(2.0f*TANFOV))
#define INV255 0.0039215686274509803f

typedef unsigned long long u64;

// ---------------- scratch (no allocations allowed) ----------------
__device__ float4 g_p0[NG], g_p1[NG], g_p3[NG];   // unsorted packed params (+bbox)
__device__ float2 g_p2[NG];
__device__ u64    g_key[NG];
__device__ int    g_tilecnt[NTILE];
__device__ float4 g_s0[NG], g_s1[NG], g_s3[NG];   // sorted
__device__ float2 g_s2[NG];
__device__ float  g_partial[RCH * 4 * NTILE * 256];

// ---------------- 1) per-gaussian preprocess (vectorized loads) ----------------
__global__ __launch_bounds__(128)
void preprocess_kernel(const float* __restrict__ means,
                       const float* __restrict__ scales_raw,
                       const float4* __restrict__ rots4,
                       const float* __restrict__ op_raw,
                       const float4* __restrict__ shs4,
                       const float* __restrict__ view,
                       const float* __restrict__ proj,
                       const float* __restrict__ campos)
{
    int n = blockIdx.x * blockDim.x + threadIdx.x;
    if (n >= NG) return;

    if (n < NTILE) g_tilecnt[n] = 0;   // per-replay reset

    float4 q4 = rots4[n];
    float sh[48];
    {
        const float4* sb = shs4 + n * 12;
        #pragma unroll
        for (int i = 0; i < 12; i++) {
            float4 v4 = sb[i];
            sh[4*i+0] = v4.x; sh[4*i+1] = v4.y; sh[4*i+2] = v4.z; sh[4*i+3] = v4.w;
        }
    }
    float mx = __ldg(means + 3*n + 0), my = __ldg(means + 3*n + 1), mz = __ldg(means + 3*n + 2);
    float sx = __expf(__ldg(scales_raw + 3*n + 0));
    float sy = __expf(__ldg(scales_raw + 3*n + 1));
    float sz = __expf(__ldg(scales_raw + 3*n + 2));
    float opr = __ldg(op_raw + n);

    float qr = q4.x, qx = q4.y, qy = q4.z, qz = q4.w;
    float qn = rsqrtf(qr*qr + qx*qx + qy*qy + qz*qz);
    qr *= qn; qx *= qn; qy *= qn; qz *= qn;

    float R00 = 1.f - 2.f*(qy*qy + qz*qz);
    float R01 = 2.f*(qx*qy - qr*qz);
    float R02 = 2.f*(qx*qz + qr*qy);
    float R10 = 2.f*(qx*qy + qr*qz);
    float R11 = 1.f - 2.f*(qx*qx + qz*qz);
    float R12 = 2.f*(qy*qz - qr*qx);
    float R20 = 2.f*(qx*qz - qr*qy);
    float R21 = 2.f*(qy*qz + qr*qx);
    float R22 = 1.f - 2.f*(qx*qx + qy*qy);

    float L00 = R00*sx, L01 = R01*sy, L02 = R02*sz;
    float L10 = R10*sx, L11 = R11*sy, L12 = R12*sz;
    float L20 = R20*sx, L21 = R21*sy, L22 = R22*sz;
    float S00 = L00*L00 + L01*L01 + L02*L02;
    float S01 = L00*L10 + L01*L11 + L02*L12;
    float S02 = L00*L20 + L01*L21 + L02*L22;
    float S11 = L10*L10 + L11*L11 + L12*L12;
    float S12 = L10*L20 + L11*L21 + L12*L22;
    float S22 = L20*L20 + L21*L21 + L22*L22;

    float v[16], p[16];
    #pragma unroll
    for (int i = 0; i < 16; i++) { v[i] = view[i]; p[i] = proj[i]; }

    float pv0 = v[0]*mx + v[1]*my + v[2]*mz + v[3];
    float pv1 = v[4]*mx + v[5]*my + v[6]*mz + v[7];
    float pv2 = v[8]*mx + v[9]*my + v[10]*mz + v[11];
    float depth = pv2;

    float ph0 = p[0]*mx + p[1]*my + p[2]*mz + p[3];
    float ph1 = p[4]*mx + p[5]*my + p[6]*mz + p[7];
    float ph3 = p[12]*mx + p[13]*my + p[14]*mz + p[15];
    float pw  = 1.f / (ph3 + 1e-7f);
    float mxs = ((ph0*pw + 1.f) * (float)IW - 1.f) * 0.5f;
    float mys = ((ph1*pw + 1.f) * (float)IH - 1.f) * 0.5f;

    float tz = depth;
    float invtz = 1.f / tz;
    float txc = fminf(fmaxf(pv0*invtz, -LIMV), LIMV) * tz;
    float tyc = fminf(fmaxf(pv1*invtz, -LIMV), LIMV) * tz;
    float J00 = FXY * invtz;
    float J02 = -FXY * txc * invtz * invtz;
    float J11 = FXY * invtz;
    float J12 = -FXY * tyc * invtz * invtz;

    float M00 = J00*v[0] + J02*v[8];
    float M01 = J00*v[1] + J02*v[9];
    float M02 = J00*v[2] + J02*v[10];
    float M10 = J11*v[4] + J12*v[8];
    float M11 = J11*v[5] + J12*v[9];
    float M12 = J11*v[6] + J12*v[10];

    float t00 = M00*S00 + M01*S01 + M02*S02;
    float t01 = M00*S01 + M01*S11 + M02*S12;
    float t02 = M00*S02 + M01*S12 + M02*S22;
    float t10 = M10*S00 + M11*S01 + M12*S02;
    float t11 = M10*S01 + M11*S11 + M12*S12;
    float t12 = M10*S02 + M11*S12 + M12*S22;
    float cov00 = t00*M00 + t01*M01 + t02*M02;
    float cov01 = t00*M10 + t01*M11 + t02*M12;
    float cov11 = t10*M10 + t11*M11 + t12*M12;

    float a  = cov00 + 0.3f;
    float bb = cov01;
    float c  = cov11 + 0.3f;
    float det = a*c - bb*bb;

    float op = 1.f / (1.f + __expf(-opr));

    float dx0 = mx - campos[0], dy0 = my - campos[1], dz0 = mz - campos[2];
    float rn = rsqrtf(dx0*dx0 + dy0*dy0 + dz0*dz0);
    float x = dx0*rn, y = dy0*rn, z = dz0*rn;
    float xx = x*x, yy = y*y, zz = z*z;
    float xy = x*y, yz = y*z, xz = x*z;

    const float C0f = 0.28209479177387814f;
    const float C1f = 0.4886025119029199f;
    const float C2f0 = 1.0925484305920792f, C2f1 = -1.0925484305920792f;
    const float C2f2 = 0.31539156525252005f, C2f3 = -1.0925484305920792f;
    const float C2f4 = 0.5462742152960396f;
    const float C3f0 = -0.5900435899266435f, C3f1 = 2.890611442640554f;
    const float C3f2 = -0.4570457994644658f, C3f3 = 0.3731763325901154f;
    const float C3f4 = -0.4570457994644658f, C3f5 = 1.445305721320277f;
    const float C3f6 = -0.5900435899266435f;

    float b1 = -C1f*y, b2 = C1f*z, b3 = -C1f*x;
    float b4 = C2f0*xy, b5 = C2f1*yz, b6 = C2f2*(2.f*zz - xx - yy);
    float b7 = C2f3*xz, b8 = C2f4*(xx - yy);
    float b9  = C3f0*y*(3.f*xx - yy);
    float b10 = C3f1*xy*z;
    float b11 = C3f2*y*(4.f*zz - xx - yy);
    float b12 = C3f3*z*(2.f*zz - 3.f*xx - 3.f*yy);
    float b13 = C3f4*x*(4.f*zz - xx - yy);
    float b14 = C3f5*z*(xx - yy);
    float b15 = C3f6*x*(xx - 3.f*yy);

    float col[3];
    #pragma unroll
    for (int ch = 0; ch < 3; ch++) {
        float res = C0f*sh[0+ch]
                  + b1*sh[3+ch]  + b2*sh[6+ch]  + b3*sh[9+ch]
                  + b4*sh[12+ch] + b5*sh[15+ch] + b6*sh[18+ch]
                  + b7*sh[21+ch] + b8*sh[24+ch]
                  + b9*sh[27+ch] + b10*sh[30+ch] + b11*sh[33+ch]
                  + b12*sh[36+ch] + b13*sh[39+ch] + b14*sh[42+ch] + b15*sh[45+ch];
        col[ch] = fmaxf(res + 0.5f, 0.f);
    }

    bool valid = (depth > 0.2f) && (det > 0.f);
    float A, B, C, pth;
    float bxmin = 1e9f, bxmax = -1e9f, bymin = 1e9f, bymax = -1e9f;
    float q2 = __logf(255.f * op) + 0.02f;
    if (valid && q2 > 0.f) {
        float invdet = 1.f / det;
        A = c * invdet;
        B = -bb * invdet;
        C = a * invdet;
        pth = -q2;
        float dxm = sqrtf(2.f * q2 * a) + 1e-3f;
        float dym = sqrtf(2.f * q2 * c) + 1e-3f;
        bxmin = mxs - dxm; bxmax = mxs + dxm;
        bymin = mys - dym; bymax = mys + dym;
    } else {
        mxs = 0.f; mys = 0.f;
        A = 0.f; B = 0.f; C = 0.f;
        op = 0.f;
        pth = 1.0f;
    }

    g_p0[n] = make_float4(mxs, mys, A, B);
    g_p1[n] = make_float4(C, op, col[0], col[1]);
    g_p2[n] = make_float2(col[2], pth);
    g_p3[n] = make_float4(bxmin, bxmax, bymin, bymax);

    unsigned int b32 = __float_as_uint(depth);
    b32 ^= (b32 >> 31) ? 0xFFFFFFFFu : 0x80000000u;
    g_key[n] = ((u64)b32 << 32) | (unsigned int)n;
}

// ---------------- 2) fused rank sort + scatter (bank-conflict-free, padded) ----------------
// 128 blocks x 256 threads; 8 threads (slices) per element, each scans 512 keys.
// Padded slice stride 257 u64: bank = (2*slice + 2*j) mod 32 -> 8 distinct banks.
#define SLICE_PAD 257
__global__ __launch_bounds__(256)
void rank_scatter_kernel()
{
    __shared__ u64 keys[8 * SLICE_PAD];   // ~16.1 KB
    int t = threadIdx.x;
    int blk = blockIdx.x;
    int elem  = blk * 32 + (t >> 3);
    int slice = t & 7;
    u64 myk = g_key[elem];
    int cnt = 0;
    #pragma unroll
    for (int st = 0; st < 2; st++) {
        // group u of this stage IS slice u: thread t stages keys[u*257 + t]
        #pragma unroll
        for (int u = 0; u < 8; u++)
            keys[u * SLICE_PAD + t] = g_key[st*2048 + u*256 + t];
        __syncthreads();
        int kb = slice * SLICE_PAD;
        #pragma unroll 8
        for (int j = 0; j < 256; j++)
            cnt += (keys[kb + j] < myk) ? 1 : 0;
        __syncthreads();
    }
    cnt += __shfl_xor_sync(0xffffffffu, cnt, 1);
    cnt += __shfl_xor_sync(0xffffffffu, cnt, 2);
    cnt += __shfl_xor_sync(0xffffffffu, cnt, 4);
    if (slice == 0) {
        g_s0[cnt] = g_p0[elem];
        g_s1[cnt] = g_p1[elem];
        g_s2[cnt] = g_p2[elem];
        g_s3[cnt] = g_p3[elem];
    }
}

// ---------------- 3) tiled render (single small batch) + fused tail combine ----------------
__global__ __launch_bounds__(256)
void render_tile_kernel(const float* __restrict__ bg, float* __restrict__ out)
{
    __shared__ float4 c0[RCHSZ];
    __shared__ float4 c1[RCHSZ];
    __shared__ float2 c2[RCHSZ];
    __shared__ int wcnt[4];
    __shared__ int sdone;

    int tile  = blockIdx.x;
    int chunk = blockIdx.y;
    int t = threadIdx.x;
    int w = t >> 5, lane = t & 31;

    float tx0 = (float)((tile % 6) * 16);
    float ty0 = (float)((tile / 6) * 16);
    float tx1 = tx0 + 15.f;
    float ty1 = ty0 + 15.f;
    float px = tx0 + (float)(t & 15);
    float py = ty0 + (float)(t >> 4);

    float T = 1.f, cr = 0.f, cg = 0.f, cb = 0.f;

    // cull: first 128 threads test this chunk's 128 bboxes
    bool hit = false;
    int gi = chunk * RCHSZ + t;
    if (t < RCHSZ) {
        float4 bbx = g_s3[gi];
        hit = (bbx.x <= tx1) && (bbx.y >= tx0) && (bbx.z <= ty1) && (bbx.w >= ty0);
    }
    unsigned int bal = __ballot_sync(0xffffffffu, hit);
    if (lane == 0 && w < 4) wcnt[w] = __popc(bal);
    __syncthreads();

    int off = 0, m = 0;
    #pragma unroll
    for (int i = 0; i < 4; i++) {
        int cnt = wcnt[i];
        if (i < w) off += cnt;
        m += cnt;
    }
    if (hit) {
        int pos = off + __popc(bal & ((1u << lane) - 1u));
        c0[pos] = g_s0[gi];
        c1[pos] = g_s1[gi];
        c2[pos] = g_s2[gi];
    }
    __syncthreads();

    for (int i = 0; i < m; i++) {
        float4 a0 = c0[i];
        float2 a2 = c2[i];
        float dx = px - a0.x;
        float dy = py - a0.y;
        float4 a1 = c1[i];
        float power = -0.5f * (a0.z*dx*dx + a1.x*dy*dy) - a0.w*dx*dy;
        if (power < a2.y) continue;
        float alpha = fminf(0.99f, a1.y * __expf(power));
        if (alpha < INV255) continue;
        float wgt = alpha * T;
        cr = fmaf(wgt, a1.z, cr);
        cg = fmaf(wgt, a1.w, cg);
        cb = fmaf(wgt, a2.x, cb);
        T *= (1.f - alpha);
    }

    int pbase = (chunk * 4) * (NTILE * 256) + tile * 256 + t;
    g_partial[pbase]                 = cr;
    g_partial[pbase + NTILE*256]     = cg;
    g_partial[pbase + 2*NTILE*256]   = cb;
    g_partial[pbase + 3*NTILE*256]   = T;

    // last block per tile folds the chunks
    __threadfence();
    if (t == 0) sdone = atomicAdd(&g_tilecnt[tile], 1);
    __syncthreads();
    if (sdone == RCH - 1) {
        __threadfence();
        float Tt = 1.f, r = 0.f, g = 0.f, b = 0.f;
        #pragma unroll
        for (int k = 0; k < RCH; k++) {
            int pb = (k * 4) * (NTILE * 256) + tile * 256 + t;
            r += Tt * g_partial[pb];
            g += Tt * g_partial[pb + NTILE*256];
            b += Tt * g_partial[pb + 2*NTILE*256];
            Tt *= g_partial[pb + 3*NTILE*256];
        }
        int pix = ((tile / 6) * 16 + (t >> 4)) * IW + (tile % 6) * 16 + (t & 15);
        out[pix]          = r + Tt * bg[0];
        out[NPIX + pix]   = g + Tt * bg[1];
        out[2*NPIX + pix] = b + Tt * bg[2];
    }
}

extern "C" void kernel_launch(void* const* d_in, const int* in_sizes, int n_in,
                              void* d_out, int out_size)
{
    const float* means      = (const float*)d_in[0];
    const float* scales_raw = (const float*)d_in[1];
    const float* rots       = (const float*)d_in[2];
    const float* op_raw     = (const float*)d_in[3];
    const float* shs        = (const float*)d_in[4];
    const float* view       = (const float*)d_in[5];
    const float* proj       = (const float*)d_in[6];
    const float* campos     = (const float*)d_in[7];
    const float* bg         = (const float*)d_in[8];
    float* out = (float*)d_out;

    preprocess_kernel<<<32, 128>>>(means, scales_raw, (const float4*)rots, op_raw,
                                   (const float4*)shs, view, proj, campos);
    rank_scatter_kernel<<<128, 256>>>();
    render_tile_kernel<<<dim3(NTILE, RCH), 256>>>(bg, out);
}

// round 12
// speedup vs baseline: 3.6995x; 1.0092x over previous
#include <cuda_runtime.h>
#include <math.h>

#define NG    4096
#define IW    96
#define IH    96
#define NPIX  (IW*IH)
#define NTILE 36            // 6x6 tiles of 16x16
#define RCH   32            // depth chunks for render parallelism
#define RCHSZ (NG/RCH)      // 128
#define TANFOV 0.36502849177392513f
#define LIMV   (1.3f*TANFOV)
#define FXY    (96.0f/(2.0f*TANFOV))
#define INV255 0.0039215686274509803f

typedef unsigned long long u64;

// ---------------- scratch (no allocations allowed) ----------------
__device__ float4 g_p0[NG], g_p1[NG], g_p3[NG];   // unsorted packed params (+bbox)
__device__ float2 g_p2[NG];
__device__ u64    g_key[NG];
__device__ int    g_tilecnt[NTILE];
__device__ float4 g_s0[NG], g_s1[NG], g_s3[NG];   // sorted
__device__ float2 g_s2[NG];
__device__ float  g_partial[RCH * 4 * NTILE * 256];

// ---------------- 1) per-gaussian preprocess (1 warp/SM, 128 blocks) ----------------
__global__
void preprocess_kernel(const float* __restrict__ means,
                       const float* __restrict__ scales_raw,
                       const float4* __restrict__ rots4,
                       const float* __restrict__ op_raw,
                       const float4* __restrict__ shs4,
                       const float* __restrict__ view,
                       const float* __restrict__ proj,
                       const float* __restrict__ campos)
{
    int n = blockIdx.x * 32 + threadIdx.x;
    if (n >= NG) return;

    if (n < NTILE) g_tilecnt[n] = 0;   // per-replay reset

    float4 q4 = rots4[n];
    float sh[48];
    {
        const float4* sb = shs4 + n * 12;
        #pragma unroll
        for (int i = 0; i < 12; i++) {
            float4 v4 = sb[i];
            sh[4*i+0] = v4.x; sh[4*i+1] = v4.y; sh[4*i+2] = v4.z; sh[4*i+3] = v4.w;
        }
    }
    float mx = __ldg(means + 3*n + 0), my = __ldg(means + 3*n + 1), mz = __ldg(means + 3*n + 2);
    float sx = __expf(__ldg(scales_raw + 3*n + 0));
    float sy = __expf(__ldg(scales_raw + 3*n + 1));
    float sz = __expf(__ldg(scales_raw + 3*n + 2));
    float opr = __ldg(op_raw + n);

    float qr = q4.x, qx = q4.y, qy = q4.z, qz = q4.w;
    float qn = rsqrtf(qr*qr + qx*qx + qy*qy + qz*qz);
    qr *= qn; qx *= qn; qy *= qn; qz *= qn;

    float R00 = 1.f - 2.f*(qy*qy + qz*qz);
    float R01 = 2.f*(qx*qy - qr*qz);
    float R02 = 2.f*(qx*qz + qr*qy);
    float R10 = 2.f*(qx*qy + qr*qz);
    float R11 = 1.f - 2.f*(qx*qx + qz*qz);
    float R12 = 2.f*(qy*qz - qr*qx);
    float R20 = 2.f*(qx*qz - qr*qy);
    float R21 = 2.f*(qy*qz + qr*qx);
    float R22 = 1.f - 2.f*(qx*qx + qy*qy);

    float L00 = R00*sx, L01 = R01*sy, L02 = R02*sz;
    float L10 = R10*sx, L11 = R11*sy, L12 = R12*sz;
    float L20 = R20*sx, L21 = R21*sy, L22 = R22*sz;
    float S00 = L00*L00 + L01*L01 + L02*L02;
    float S01 = L00*L10 + L01*L11 + L02*L12;
    float S02 = L00*L20 + L01*L21 + L02*L22;
    float S11 = L10*L10 + L11*L11 + L12*L12;
    float S12 = L10*L20 + L11*L21 + L12*L22;
    float S22 = L20*L20 + L21*L21 + L22*L22;

    float v[16], p[16];
    #pragma unroll
    for (int i = 0; i < 16; i++) { v[i] = view[i]; p[i] = proj[i]; }

    float pv0 = v[0]*mx + v[1]*my + v[2]*mz + v[3];
    float pv1 = v[4]*mx + v[5]*my + v[6]*mz + v[7];
    float pv2 = v[8]*mx + v[9]*my + v[10]*mz + v[11];
    float depth = pv2;

    float ph0 = p[0]*mx + p[1]*my + p[2]*mz + p[3];
    float ph1 = p[4]*mx + p[5]*my + p[6]*mz + p[7];
    float ph3 = p[12]*mx + p[13]*my + p[14]*mz + p[15];
    float pw  = 1.f / (ph3 + 1e-7f);
    float mxs = ((ph0*pw + 1.f) * (float)IW - 1.f) * 0.5f;
    float mys = ((ph1*pw + 1.f) * (float)IH - 1.f) * 0.5f;

    float tz = depth;
    float invtz = 1.f / tz;
    float txc = fminf(fmaxf(pv0*invtz, -LIMV), LIMV) * tz;
    float tyc = fminf(fmaxf(pv1*invtz, -LIMV), LIMV) * tz;
    float J00 = FXY * invtz;
    float J02 = -FXY * txc * invtz * invtz;
    float J11 = FXY * invtz;
    float J12 = -FXY * tyc * invtz * invtz;

    float M00 = J00*v[0] + J02*v[8];
    float M01 = J00*v[1] + J02*v[9];
    float M02 = J00*v[2] + J02*v[10];
    float M10 = J11*v[4] + J12*v[8];
    float M11 = J11*v[5] + J12*v[9];
    float M12 = J11*v[6] + J12*v[10];

    float t00 = M00*S00 + M01*S01 + M02*S02;
    float t01 = M00*S01 + M01*S11 + M02*S12;
    float t02 = M00*S02 + M01*S12 + M02*S22;
    float t10 = M10*S00 + M11*S01 + M12*S02;
    float t11 = M10*S01 + M11*S11 + M12*S12;
    float t12 = M10*S02 + M11*S12 + M12*S22;
    float cov00 = t00*M00 + t01*M01 + t02*M02;
    float cov01 = t00*M10 + t01*M11 + t02*M12;
    float cov11 = t10*M10 + t11*M11 + t12*M12;

    float a  = cov00 + 0.3f;
    float bb = cov01;
    float c  = cov11 + 0.3f;
    float det = a*c - bb*bb;

    float op = 1.f / (1.f + __expf(-opr));

    float dx0 = mx - campos[0], dy0 = my - campos[1], dz0 = mz - campos[2];
    float rn = rsqrtf(dx0*dx0 + dy0*dy0 + dz0*dz0);
    float x = dx0*rn, y = dy0*rn, z = dz0*rn;
    float xx = x*x, yy = y*y, zz = z*z;
    float xy = x*y, yz = y*z, xz = x*z;

    const float C0f = 0.28209479177387814f;
    const float C1f = 0.4886025119029199f;
    const float C2f0 = 1.0925484305920792f, C2f1 = -1.0925484305920792f;
    const float C2f2 = 0.31539156525252005f, C2f3 = -1.0925484305920792f;
    const float C2f4 = 0.5462742152960396f;
    const float C3f0 = -0.5900435899266435f, C3f1 = 2.890611442640554f;
    const float C3f2 = -0.4570457994644658f, C3f3 = 0.3731763325901154f;
    const float C3f4 = -0.4570457994644658f, C3f5 = 1.445305721320277f;
    const float C3f6 = -0.5900435899266435f;

    float b1 = -C1f*y, b2 = C1f*z, b3 = -C1f*x;
    float b4 = C2f0*xy, b5 = C2f1*yz, b6 = C2f2*(2.f*zz - xx - yy);
    float b7 = C2f3*xz, b8 = C2f4*(xx - yy);
    float b9  = C3f0*y*(3.f*xx - yy);
    float b10 = C3f1*xy*z;
    float b11 = C3f2*y*(4.f*zz - xx - yy);
    float b12 = C3f3*z*(2.f*zz - 3.f*xx - 3.f*yy);
    float b13 = C3f4*x*(4.f*zz - xx - yy);
    float b14 = C3f5*z*(xx - yy);
    float b15 = C3f6*x*(xx - 3.f*yy);

    float col[3];
    #pragma unroll
    for (int ch = 0; ch < 3; ch++) {
        float res = C0f*sh[0+ch]
                  + b1*sh[3+ch]  + b2*sh[6+ch]  + b3*sh[9+ch]
                  + b4*sh[12+ch] + b5*sh[15+ch] + b6*sh[18+ch]
                  + b7*sh[21+ch] + b8*sh[24+ch]
                  + b9*sh[27+ch] + b10*sh[30+ch] + b11*sh[33+ch]
                  + b12*sh[36+ch] + b13*sh[39+ch] + b14*sh[42+ch] + b15*sh[45+ch];
        col[ch] = fmaxf(res + 0.5f, 0.f);
    }

    bool valid = (depth > 0.2f) && (det > 0.f);
    float A, B, C, pth;
    float bxmin = 1e9f, bxmax = -1e9f, bymin = 1e9f, bymax = -1e9f;
    float q2 = __logf(255.f * op) + 0.02f;
    if (valid && q2 > 0.f) {
        float invdet = 1.f / det;
        A = c * invdet;
        B = -bb * invdet;
        C = a * invdet;
        pth = -q2;
        float dxm = sqrtf(2.f * q2 * a) + 1e-3f;
        float dym = sqrtf(2.f * q2 * c) + 1e-3f;
        bxmin = mxs - dxm; bxmax = mxs + dxm;
        bymin = mys - dym; bymax = mys + dym;
    } else {
        mxs = 0.f; mys = 0.f;
        A = 0.f; B = 0.f; C = 0.f;
        op = 0.f;
        pth = 1.0f;
    }

    g_p0[n] = make_float4(mxs, mys, A, B);
    g_p1[n] = make_float4(C, op, col[0], col[1]);
    g_p2[n] = make_float2(col[2], pth);
    g_p3[n] = make_float4(bxmin, bxmax, bymin, bymax);

    unsigned int b32 = __float_as_uint(depth);
    b32 ^= (b32 >> 31) ? 0xFFFFFFFFu : 0x80000000u;
    g_key[n] = ((u64)b32 << 32) | (unsigned int)n;
}

// ---------------- 2) fused rank sort + scatter (bank-conflict-free, padded) ----------------
#define SLICE_PAD 257
__global__ __launch_bounds__(256)
void rank_scatter_kernel()
{
    __shared__ u64 keys[8 * SLICE_PAD];   // ~16.1 KB
    int t = threadIdx.x;
    int blk = blockIdx.x;
    int elem  = blk * 32 + (t >> 3);
    int slice = t & 7;
    u64 myk = g_key[elem];
    int cnt = 0;
    #pragma unroll
    for (int st = 0; st < 2; st++) {
        #pragma unroll
        for (int u = 0; u < 8; u++)
            keys[u * SLICE_PAD + t] = g_key[st*2048 + u*256 + t];
        __syncthreads();
        int kb = slice * SLICE_PAD;
        #pragma unroll 8
        for (int j = 0; j < 256; j++)
            cnt += (keys[kb + j] < myk) ? 1 : 0;
        __syncthreads();
    }
    cnt += __shfl_xor_sync(0xffffffffu, cnt, 1);
    cnt += __shfl_xor_sync(0xffffffffu, cnt, 2);
    cnt += __shfl_xor_sync(0xffffffffu, cnt, 4);
    if (slice == 0) {
        g_s0[cnt] = g_p0[elem];
        g_s1[cnt] = g_p1[elem];
        g_s2[cnt] = g_p2[elem];
        g_s3[cnt] = g_p3[elem];
    }
}

// ---------------- 3) tiled render (single small batch) + fused tail combine ----------------
__global__ __launch_bounds__(256)
void render_tile_kernel(const float* __restrict__ bg, float* __restrict__ out)
{
    __shared__ float4 c0[RCHSZ];
    __shared__ float4 c1[RCHSZ];
    __shared__ float2 c2[RCHSZ];
    __shared__ int wcnt[4];
    __shared__ int sdone;

    int tile  = blockIdx.x;
    int chunk = blockIdx.y;
    int t = threadIdx.x;
    int w = t >> 5, lane = t & 31;

    float tx0 = (float)((tile % 6) * 16);
    float ty0 = (float)((tile / 6) * 16);
    float tx1 = tx0 + 15.f;
    float ty1 = ty0 + 15.f;
    float px = tx0 + (float)(t & 15);
    float py = ty0 + (float)(t >> 4);

    float T = 1.f, cr = 0.f, cg = 0.f, cb = 0.f;

    bool hit = false;
    int gi = chunk * RCHSZ + t;
    if (t < RCHSZ) {
        float4 bbx = g_s3[gi];
        hit = (bbx.x <= tx1) && (bbx.y >= tx0) && (bbx.z <= ty1) && (bbx.w >= ty0);
    }
    unsigned int bal = __ballot_sync(0xffffffffu, hit);
    if (lane == 0 && w < 4) wcnt[w] = __popc(bal);
    __syncthreads();

    int off = 0, m = 0;
    #pragma unroll
    for (int i = 0; i < 4; i++) {
        int cnt = wcnt[i];
        if (i < w) off += cnt;
        m += cnt;
    }
    if (hit) {
        int pos = off + __popc(bal & ((1u << lane) - 1u));
        c0[pos] = g_s0[gi];
        c1[pos] = g_s1[gi];
        c2[pos] = g_s2[gi];
    }
    __syncthreads();

    for (int i = 0; i < m; i++) {
        float4 a0 = c0[i];
        float2 a2 = c2[i];
        float dx = px - a0.x;
        float dy = py - a0.y;
        float4 a1 = c1[i];
        float power = -0.5f * (a0.z*dx*dx + a1.x*dy*dy) - a0.w*dx*dy;
        if (power < a2.y) continue;
        float alpha = fminf(0.99f, a1.y * __expf(power));
        if (alpha < INV255) continue;
        float wgt = alpha * T;
        cr = fmaf(wgt, a1.z, cr);
        cg = fmaf(wgt, a1.w, cg);
        cb = fmaf(wgt, a2.x, cb);
        T *= (1.f - alpha);
    }

    int pbase = (chunk * 4) * (NTILE * 256) + tile * 256 + t;
    g_partial[pbase]                 = cr;
    g_partial[pbase + NTILE*256]     = cg;
    g_partial[pbase + 2*NTILE*256]   = cb;
    g_partial[pbase + 3*NTILE*256]   = T;

    __threadfence();
    if (t == 0) sdone = atomicAdd(&g_tilecnt[tile], 1);
    __syncthreads();
    if (sdone == RCH - 1) {
        __threadfence();
        float Tt = 1.f, r = 0.f, g = 0.f, b = 0.f;
        #pragma unroll
        for (int k = 0; k < RCH; k++) {
            int pb = (k * 4) * (NTILE * 256) + tile * 256 + t;
            r += Tt * g_partial[pb];
            g += Tt * g_partial[pb + NTILE*256];
            b += Tt * g_partial[pb + 2*NTILE*256];
            Tt *= g_partial[pb + 3*NTILE*256];
        }
        int pix = ((tile / 6) * 16 + (t >> 4)) * IW + (tile % 6) * 16 + (t & 15);
        out[pix]          = r + Tt * bg[0];
        out[NPIX + pix]   = g + Tt * bg[1];
        out[2*NPIX + pix] = b + Tt * bg[2];
    }
}

extern "C" void kernel_launch(void* const* d_in, const int* in_sizes, int n_in,
                              void* d_out, int out_size)
{
    const float* means      = (const float*)d_in[0];
    const float* scales_raw = (const float*)d_in[1];
    const float* rots       = (const float*)d_in[2];
    const float* op_raw     = (const float*)d_in[3];
    const float* shs        = (const float*)d_in[4];
    const float* view       = (const float*)d_in[5];
    const float* proj       = (const float*)d_in[6];
    const float* campos     = (const float*)d_in[7];
    const float* bg         = (const float*)d_in[8];
    float* out = (float*)d_out;

    preprocess_kernel<<<128, 32>>>(means, scales_raw, (const float4*)rots, op_raw,
                                   (const float4*)shs, view, proj, campos);
    rank_scatter_kernel<<<128, 256>>>();
    render_tile_kernel<<<dim3(NTILE, RCH), 256>>>(bg, out);
}